// round 9
// baseline (speedup 1.0000x reference)
#include <cuda_runtime.h>
#include <cuda_bf16.h>
#include <math.h>
#include <stdint.h>

#define DDIM 256
#define NQMAX 40000

// ---------------- scratch (device globals; zero-initialized, no allocation) --
__device__ __align__(16) float g_v   [NQMAX * DDIM];
__device__ __align__(16) float g_oa  [NQMAX * 144];
__device__ __align__(16) float g_msda[NQMAX * DDIM];
__device__ __align__(16) float g_tmp [NQMAX * DDIM];
__device__ __align__(16) float g_y   [NQMAX * DDIM];

// transposed + bf16-split weights: [N][K=256]   (oa padded to 256 rows, zeros)
__device__ __align__(16) __nv_bfloat16 g_bv_h[DDIM * DDIM];
__device__ __align__(16) __nv_bfloat16 g_bv_l[DDIM * DDIM];
__device__ __align__(16) __nv_bfloat16 g_bo_h[DDIM * DDIM];
__device__ __align__(16) __nv_bfloat16 g_bo_l[DDIM * DDIM];
__device__ __align__(16) __nv_bfloat16 g_b1_h[DDIM * DDIM];
__device__ __align__(16) __nv_bfloat16 g_b1_l[DDIM * DDIM];
__device__ __align__(16) __nv_bfloat16 g_b2_h[DDIM * DDIM];
__device__ __align__(16) __nv_bfloat16 g_b2_l[DDIM * DDIM];
__device__ __align__(16) __nv_bfloat16 g_boa_h[DDIM * DDIM];
__device__ __align__(16) __nv_bfloat16 g_boa_l[DDIM * DDIM];
__device__ __align__(16) float g_boa[144];

// ---------------- helpers ------------------------------------------------------
__device__ __forceinline__ uint32_t smem_u32(const void* p) {
    uint32_t a;
    asm("{ .reg .u64 t; cvta.to.shared.u64 t, %1; cvt.u32.u64 %0, t; }" : "=r"(a) : "l"(p));
    return a;
}

__device__ __forceinline__ uint32_t pack_bf16(__nv_bfloat16 x, __nv_bfloat16 y) {
    __nv_bfloat162 t(x, y);
    return *reinterpret_cast<uint32_t*>(&t);
}

__device__ __forceinline__ float gelu_exact(float x) {
    return 0.5f * x * (1.0f + erff(x * 0.70710678118654752f));
}

#define LDSM4(r, addr) \
    asm volatile("ldmatrix.sync.aligned.m8n8.x4.shared.b16 {%0,%1,%2,%3}, [%4];" \
        : "=r"((r)[0]), "=r"((r)[1]), "=r"((r)[2]), "=r"((r)[3]) : "r"(addr))

#define CP_ASYNC16(dst, src) \
    asm volatile("cp.async.ca.shared.global [%0], [%1], 16;" :: "r"(dst), "l"(src))
#define CP_COMMIT() asm volatile("cp.async.commit_group;" ::: "memory")
#define CP_WAIT(n)  asm volatile("cp.async.wait_group %0;" :: "n"(n) : "memory")

__device__ __forceinline__ void mma_bf16(float* d, const uint32_t* a,
                                         uint32_t b0, uint32_t b1) {
    asm volatile(
        "mma.sync.aligned.m16n8k16.row.col.f32.bf16.bf16.f32 "
        "{%0,%1,%2,%3}, {%4,%5,%6,%7}, {%8,%9}, {%0,%1,%2,%3};"
        : "+f"(d[0]), "+f"(d[1]), "+f"(d[2]), "+f"(d[3])
        : "r"(a[0]), "r"(a[1]), "r"(a[2]), "r"(a[3]), "r"(b0), "r"(b1));
}

// ---------------- HMMA GEMM v5: 64x128 CTA tile, 3 CTAs/SM ---------------------
// C = A[M][256] @ B^T + bias.  CTA tile 64x128, 8 warps (2x4), warp tile 32x32.
// MODE 0: +bias; MODE 1: +bias then exact GELU.
// FULLN=1: all warp columns valid. FULLN=0: clamp via unrolled break (no spills).
template<int MODE, int FULLN>
__global__ __launch_bounds__(256, 3)
void gemm_mma(const float* __restrict__ A,
              const __nv_bfloat16* __restrict__ Bh,
              const __nv_bfloat16* __restrict__ Bl,
              const float* __restrict__ bias,
              float* __restrict__ C, int M, int N) {
    extern __shared__ __align__(128) char smem[];
    const uint32_t sb = smem_u32(smem);
    const int tid = threadIdx.x;
    const int wid = tid >> 5;
    const int lane = tid & 31;
    const int m0 = blockIdx.y * 64;
    const int n0 = blockIdx.x * 128;
    const int wr = wid & 1;        // 2 row-groups of 32
    const int wc = wid >> 1;       // 4 col-groups of 32

    constexpr int RB = 48;                 // smem row bytes (32 data + 16 pad)
    constexpr int STG_A = 64 * RB;         // 3072
    constexpr int STG_B = 128 * RB;        // 6144
    constexpr int SSTR  = 2 * STG_A + 2 * STG_B;  // 18432 per stage
    const uint32_t offAh = 0, offAl = STG_A, offBh = 2 * STG_A, offBl = 2 * STG_A + STG_B;

    // valid nb count for this warp (16-col groups inside its 32-col slab)
    int nbLim = 2;
    if (!FULLN) {
        const int rem = N - n0 - wc * 32;
        nbLim = rem >= 32 ? 2 : (rem <= 0 ? 0 : (rem + 15) >> 4);
    }

    float acc[2][4][4];
#pragma unroll
    for (int i = 0; i < 2; ++i)
#pragma unroll
        for (int j = 0; j < 4; ++j)
#pragma unroll
            for (int k = 0; k < 4; ++k) acc[i][j][k] = 0.f;

    float4 pa;                             // one float4 slot per thread (64 rows x 4)
    const int brow = tid >> 1;
    const int bcol = (tid & 1) * 16;
    const __nv_bfloat16* bSrcH = Bh + (size_t)(n0 + brow) * DDIM + (tid & 1) * 8;
    const __nv_bfloat16* bSrcL = Bl + (size_t)(n0 + brow) * DDIM + (tid & 1) * 8;
    const uint32_t bDstOff = brow * RB + bcol;

#define ISSUE_B(c, s) do { \
    CP_ASYNC16(sb + offBh + (s) * SSTR + bDstOff, bSrcH + (c) * 16); \
    CP_ASYNC16(sb + offBl + (s) * SSTR + bDstOff, bSrcL + (c) * 16); \
    CP_COMMIT(); } while (0)

#define LOAD_A(c) do { \
    const int r = tid >> 2, qq = tid & 3; \
    if (m0 + r < M) \
        pa = *reinterpret_cast<const float4*>(A + (size_t)(m0 + r) * DDIM + (c) * 16 + qq * 4); \
    else pa = make_float4(0.f, 0.f, 0.f, 0.f); \
} while (0)

#define STORE_A(s) do { \
    const int r = tid >> 2, qq = tid & 3; \
    __nv_bfloat16 h0 = __float2bfloat16(pa.x); \
    __nv_bfloat16 h1 = __float2bfloat16(pa.y); \
    __nv_bfloat16 h2 = __float2bfloat16(pa.z); \
    __nv_bfloat16 h3 = __float2bfloat16(pa.w); \
    uint2 hv = make_uint2(pack_bf16(h0, h1), pack_bf16(h2, h3)); \
    uint2 lv = make_uint2( \
        pack_bf16(__float2bfloat16(pa.x - __bfloat162float(h0)), \
                  __float2bfloat16(pa.y - __bfloat162float(h1))), \
        pack_bf16(__float2bfloat16(pa.z - __bfloat162float(h2)), \
                  __float2bfloat16(pa.w - __bfloat162float(h3)))); \
    *reinterpret_cast<uint2*>(smem + offAh + (s) * SSTR + r * RB + qq * 8) = hv; \
    *reinterpret_cast<uint2*>(smem + offAl + (s) * SSTR + r * RB + qq * 8) = lv; \
} while (0)

    ISSUE_B(0, 0);
    LOAD_A(0);

    const uint32_t lmA = (wr * 32 + (lane & 15)) * RB + (lane >> 4) * 16;
    const uint32_t lmB = (wc * 32 + (lane & 15)) * RB + (lane >> 4) * 16;

    for (int c = 0; c < 16; ++c) {
        const int s = c & 1;
        STORE_A(s);
        if (c < 15) { ISSUE_B(c + 1, s ^ 1); CP_WAIT(1); }
        else        { CP_WAIT(0); }
        __syncthreads();
        if (c < 15) LOAD_A(c + 1);

        uint32_t ah[2][4], al[2][4];
#pragma unroll
        for (int mr = 0; mr < 2; ++mr) {
            LDSM4(ah[mr], sb + offAh + s * SSTR + lmA + mr * 16 * RB);
            LDSM4(al[mr], sb + offAl + s * SSTR + lmA + mr * 16 * RB);
        }
#pragma unroll
        for (int nb = 0; nb < 2; ++nb) {          // constant trip count
            if (!FULLN && nb >= nbLim) break;
            uint32_t bh[4], bl[4];
            LDSM4(bh, sb + offBh + s * SSTR + lmB + nb * 16 * RB);
            LDSM4(bl, sb + offBl + s * SSTR + lmB + nb * 16 * RB);
#pragma unroll
            for (int mr = 0; mr < 2; ++mr) {
                mma_bf16(acc[mr][nb * 2 + 0], ah[mr], bh[0], bh[2]);
                mma_bf16(acc[mr][nb * 2 + 1], ah[mr], bh[1], bh[3]);
                mma_bf16(acc[mr][nb * 2 + 0], ah[mr], bl[0], bl[2]);
                mma_bf16(acc[mr][nb * 2 + 1], ah[mr], bl[1], bl[3]);
                mma_bf16(acc[mr][nb * 2 + 0], al[mr], bh[0], bh[2]);
                mma_bf16(acc[mr][nb * 2 + 1], al[mr], bh[1], bh[3]);
            }
        }
        __syncthreads();
    }

    // ---- epilogue ----
#pragma unroll
    for (int mr = 0; mr < 2; ++mr) {
        const int r0 = m0 + wr * 32 + mr * 16 + (lane >> 2);
#pragma unroll
        for (int f = 0; f < 4; ++f) {
            const int col = n0 + wc * 32 + f * 8 + (lane & 3) * 2;
            if (col >= N) continue;
            const float b0 = bias[col], b1 = bias[col + 1];
#pragma unroll
            for (int h = 0; h < 2; ++h) {
                const int row = r0 + h * 8;
                if (row >= M) continue;
                float x0 = acc[mr][f][h * 2 + 0] + b0;
                float x1 = acc[mr][f][h * 2 + 1] + b1;
                if (MODE == 1) { x0 = gelu_exact(x0); x1 = gelu_exact(x1); }
                *reinterpret_cast<float2*>(C + (size_t)row * N + col) = make_float2(x0, x1);
            }
        }
    }
#undef ISSUE_B
#undef LOAD_A
#undef STORE_A
}

// ---------------- weight transpose + bf16 split (once per launch) -------------
__global__ __launch_bounds__(256)
void convert_weights(const float* __restrict__ Wv, const float* __restrict__ Wo,
                     const float* __restrict__ W1, const float* __restrict__ W2,
                     const float* __restrict__ Woff, const float* __restrict__ Wattn,
                     const float* __restrict__ boff, const float* __restrict__ battn) {
    const int b = blockIdx.x;
    const int k = threadIdx.x;
    if (b == 1168) {
        if (k < 96) g_boa[k] = boff[k];
        else if (k < 144) g_boa[k] = battn[k - 96];
        return;
    }
    const float* W; __nv_bfloat16* oh; __nv_bfloat16* ol; int n, nout, N;
    if (b < 256)       { W = Wv; oh = g_bv_h; ol = g_bv_l; n = b;        nout = n; N = 256; }
    else if (b < 512)  { W = Wo; oh = g_bo_h; ol = g_bo_l; n = b - 256;  nout = n; N = 256; }
    else if (b < 768)  { W = W1; oh = g_b1_h; ol = g_b1_l; n = b - 512;  nout = n; N = 256; }
    else if (b < 1024) { W = W2; oh = g_b2_h; ol = g_b2_l; n = b - 768;  nout = n; N = 256; }
    else {
        nout = b - 1024;  // 0..143
        oh = g_boa_h; ol = g_boa_l;
        if (nout < 96) { W = Woff;  n = nout;      N = 96; }
        else           { W = Wattn; n = nout - 96; N = 48; }
    }
    const float x = W[(size_t)k * N + n];
    const __nv_bfloat16 h = __float2bfloat16(x);
    const __nv_bfloat16 l = __float2bfloat16(x - __bfloat162float(h));
    oh[(size_t)nout * DDIM + k] = h;
    ol[(size_t)nout * DDIM + k] = l;
}

// ---------------- MSDA sampling: corner-parallel float4 gathers ---------------
__global__ __launch_bounds__(256)
void msda_sample_kernel(const float* __restrict__ oa, const float* __restrict__ v,
                        const float* __restrict__ ref, const int* __restrict__ ss,
                        float* __restrict__ out) {
    const int q = blockIdx.x;
    const int h = threadIdx.x >> 5;
    const int lane = threadIdx.x & 31;
    const int corner = lane >> 3;
    const int dx = corner & 1;
    const int dy = corner >> 1;
    const int cg = lane & 7;

    const int H = ss[0];
    const int W = ss[1];

    const float bx = __ldg(ref + q * 2 + 0) * (float)W - 0.5f;
    const float by = __ldg(ref + q * 2 + 1) * (float)H - 0.5f;

    const float* qa = oa + (size_t)q * 144;
    float lg[6];
    float mx = -1e30f;
#pragma unroll
    for (int p = 0; p < 6; ++p) {
        lg[p] = __ldg(qa + 96 + h * 6 + p);
        mx = fmaxf(mx, lg[p]);
    }
    float s = 0.f;
#pragma unroll
    for (int p = 0; p < 6; ++p) { lg[p] = __expf(lg[p] - mx); s += lg[p]; }
    const float inv = 1.f / s;

    const float4* vh = reinterpret_cast<const float4*>(v) + (h * 8 + cg);
    float4 acc = make_float4(0.f, 0.f, 0.f, 0.f);

#pragma unroll
    for (int p = 0; p < 6; ++p) {
        const float ox = __ldg(qa + h * 12 + p * 2 + 0);
        const float oy = __ldg(qa + h * 12 + p * 2 + 1);
        const float lx = bx + ox;
        const float ly = by + oy;
        const float x0f = floorf(lx);
        const float y0f = floorf(ly);
        const float fx = lx - x0f;
        const float fy = ly - y0f;
        const int xi = (int)x0f + dx;
        const int yi = (int)y0f + dy;
        const float wx = dx ? fx : 1.f - fx;
        const float wy = dy ? fy : 1.f - fy;
        const bool valid = (xi >= 0) & (xi < W) & (yi >= 0) & (yi < H);
        const float w = valid ? (lg[p] * inv) * wx * wy : 0.f;
        const uint32_t xc = (uint32_t)min(max(xi, 0), W - 1);
        const uint32_t yc = (uint32_t)min(max(yi, 0), H - 1);
        const uint32_t off = (yc * (uint32_t)W + xc) * 64u;
        const float4 val = __ldg(vh + off);
        acc.x += w * val.x;
        acc.y += w * val.y;
        acc.z += w * val.z;
        acc.w += w * val.w;
    }

#pragma unroll
    for (int o = 8; o <= 16; o <<= 1) {
        acc.x += __shfl_xor_sync(0xffffffffu, acc.x, o);
        acc.y += __shfl_xor_sync(0xffffffffu, acc.y, o);
        acc.z += __shfl_xor_sync(0xffffffffu, acc.z, o);
        acc.w += __shfl_xor_sync(0xffffffffu, acc.w, o);
    }
    if (lane < 8)
        *reinterpret_cast<float4*>(out + (size_t)q * DDIM + h * 32 + cg * 4) = acc;
}

// ---------------- fused residual + LayerNorm -----------------------------------
__global__ __launch_bounds__(256)
void ln_kernel(const float* __restrict__ x, const float* __restrict__ res,
               const float* __restrict__ g, const float* __restrict__ b,
               float* __restrict__ out) {
    const int row = blockIdx.x;
    const int tid = threadIdx.x;
    const float v = x[(size_t)row * DDIM + tid] + res[(size_t)row * DDIM + tid];

    float s = v, s2 = v * v;
#pragma unroll
    for (int o = 16; o; o >>= 1) {
        s  += __shfl_xor_sync(0xffffffffu, s, o);
        s2 += __shfl_xor_sync(0xffffffffu, s2, o);
    }
    __shared__ float sh[16];
    const int w = tid >> 5, lane = tid & 31;
    if (lane == 0) { sh[w] = s; sh[w + 8] = s2; }
    __syncthreads();
    if (tid == 0) {
        float a = 0.f, c = 0.f;
#pragma unroll
        for (int i = 0; i < 8; ++i) { a += sh[i]; c += sh[i + 8]; }
        sh[0] = a; sh[8] = c;
    }
    __syncthreads();
    const float mean = sh[0] * (1.f / 256.f);
    const float var  = sh[8] * (1.f / 256.f) - mean * mean;
    const float rstd = rsqrtf(var + 1e-5f);
    out[(size_t)row * DDIM + tid] = (v - mean) * rstd * g[tid] + b[tid];
}

// ---------------- launch --------------------------------------------------------
extern "C" void kernel_launch(void* const* d_in, const int* in_sizes, int n_in,
                              void* d_out, int out_size) {
    const float* query  = (const float*)d_in[0];
    const float* value  = (const float*)d_in[1];
    const float* refp   = (const float*)d_in[2];
    const int*   ss     = (const int*)d_in[3];
    const float* W_off  = (const float*)d_in[5];
    const float* b_off  = (const float*)d_in[6];
    const float* W_attn = (const float*)d_in[7];
    const float* b_attn = (const float*)d_in[8];
    const float* W_val  = (const float*)d_in[9];
    const float* b_val  = (const float*)d_in[10];
    const float* W_out  = (const float*)d_in[11];
    const float* b_out  = (const float*)d_in[12];
    const float* ln1_g  = (const float*)d_in[13];
    const float* ln1_b  = (const float*)d_in[14];
    const float* W1     = (const float*)d_in[15];
    const float* b1     = (const float*)d_in[16];
    const float* W2     = (const float*)d_in[17];
    const float* b2     = (const float*)d_in[18];
    const float* ln2_g  = (const float*)d_in[19];
    const float* ln2_b  = (const float*)d_in[20];
    float* out = (float*)d_out;

    const int M  = in_sizes[0] / DDIM;
    const int Mv = in_sizes[1] / DDIM;

    float *pv, *poa, *pmsda, *ptmp, *py, *pboa;
    __nv_bfloat16 *bvh, *bvl, *boh, *bol, *b1h, *b1l, *b2h, *b2l, *boah, *boal;
    cudaGetSymbolAddress((void**)&pv,    g_v);
    cudaGetSymbolAddress((void**)&poa,   g_oa);
    cudaGetSymbolAddress((void**)&pmsda, g_msda);
    cudaGetSymbolAddress((void**)&ptmp,  g_tmp);
    cudaGetSymbolAddress((void**)&py,    g_y);
    cudaGetSymbolAddress((void**)&pboa,  g_boa);
    cudaGetSymbolAddress((void**)&bvh,   g_bv_h);
    cudaGetSymbolAddress((void**)&bvl,   g_bv_l);
    cudaGetSymbolAddress((void**)&boh,   g_bo_h);
    cudaGetSymbolAddress((void**)&bol,   g_bo_l);
    cudaGetSymbolAddress((void**)&b1h,   g_b1_h);
    cudaGetSymbolAddress((void**)&b1l,   g_b1_l);
    cudaGetSymbolAddress((void**)&b2h,   g_b2_h);
    cudaGetSymbolAddress((void**)&b2l,   g_b2_l);
    cudaGetSymbolAddress((void**)&boah,  g_boa_h);
    cudaGetSymbolAddress((void**)&boal,  g_boa_l);

    const int SMEM = 2 * (2 * 64 * 48 + 2 * 128 * 48);  // 36864 bytes
    cudaFuncSetAttribute((gemm_mma<0, 1>), cudaFuncAttributeMaxDynamicSharedMemorySize, SMEM);
    cudaFuncSetAttribute((gemm_mma<1, 1>), cudaFuncAttributeMaxDynamicSharedMemorySize, SMEM);
    cudaFuncSetAttribute((gemm_mma<0, 0>), cudaFuncAttributeMaxDynamicSharedMemorySize, SMEM);

    const int gM  = (M + 63) / 64;
    const int gMv = (Mv + 63) / 64;

    // 0) weights -> transposed bf16 hi/lo
    convert_weights<<<1169, 256>>>(W_val, W_out, W1, W2, W_off, W_attn, b_off, b_attn);
    // 1) value projection
    gemm_mma<0, 1><<<dim3(2, gMv), 256, SMEM>>>(value, bvh, bvl, b_val, pv, Mv, DDIM);
    // 2) fused offsets+attn logits GEMM (N=144, statically clamped)
    gemm_mma<0, 0><<<dim3(2, gM), 256, SMEM>>>(query, boah, boal, pboa, poa, M, 144);
    // 3) deformable sampling
    msda_sample_kernel<<<M, 256>>>(poa, pv, refp, ss, pmsda);
    // 4) output projection + residual + LN1
    gemm_mma<0, 1><<<dim3(2, gM), 256, SMEM>>>(pmsda, boh, bol, b_out, ptmp, M, DDIM);
    ln_kernel<<<M, 256>>>(ptmp, query, ln1_g, ln1_b, py);
    // 5) FFN
    gemm_mma<1, 1><<<dim3(2, gM), 256, SMEM>>>(py, b1h, b1l, b1, ptmp, M, DDIM);
    gemm_mma<0, 1><<<dim3(2, gM), 256, SMEM>>>(ptmp, b2h, b2l, b2, pmsda, M, DDIM);
    ln_kernel<<<M, 256>>>(pmsda, py, ln2_g, ln2_b, out);
}

// round 10
// speedup vs baseline: 1.0940x; 1.0940x over previous
#include <cuda_runtime.h>
#include <cuda_bf16.h>
#include <math.h>
#include <stdint.h>

#define DDIM 256
#define NQMAX 40000

// ---------------- scratch (device globals; zero-initialized, no allocation) --
__device__ __align__(16) float g_v   [NQMAX * DDIM];
__device__ __align__(16) float g_oa  [NQMAX * 144];
__device__ __align__(16) float g_msda[NQMAX * DDIM];
__device__ __align__(16) float g_tmp [NQMAX * DDIM];
__device__ __align__(16) float g_y   [NQMAX * DDIM];

// transposed + bf16-split weights: [N][K=256]   (oa padded to 256 rows, zeros)
__device__ __align__(16) __nv_bfloat16 g_bv_h[DDIM * DDIM];
__device__ __align__(16) __nv_bfloat16 g_bv_l[DDIM * DDIM];
__device__ __align__(16) __nv_bfloat16 g_bo_h[DDIM * DDIM];
__device__ __align__(16) __nv_bfloat16 g_bo_l[DDIM * DDIM];
__device__ __align__(16) __nv_bfloat16 g_b1_h[DDIM * DDIM];
__device__ __align__(16) __nv_bfloat16 g_b1_l[DDIM * DDIM];
__device__ __align__(16) __nv_bfloat16 g_b2_h[DDIM * DDIM];
__device__ __align__(16) __nv_bfloat16 g_b2_l[DDIM * DDIM];
__device__ __align__(16) __nv_bfloat16 g_boa_h[DDIM * DDIM];
__device__ __align__(16) __nv_bfloat16 g_boa_l[DDIM * DDIM];
__device__ __align__(16) float g_boa[144];

// ---------------- helpers ------------------------------------------------------
__device__ __forceinline__ uint32_t smem_u32(const void* p) {
    uint32_t a;
    asm("{ .reg .u64 t; cvta.to.shared.u64 t, %1; cvt.u32.u64 %0, t; }" : "=r"(a) : "l"(p));
    return a;
}

__device__ __forceinline__ uint32_t pack_bf16(__nv_bfloat16 x, __nv_bfloat16 y) {
    __nv_bfloat162 t(x, y);
    return *reinterpret_cast<uint32_t*>(&t);
}

__device__ __forceinline__ float gelu_exact(float x) {
    return 0.5f * x * (1.0f + erff(x * 0.70710678118654752f));
}

#define LDSM4(r, addr) \
    asm volatile("ldmatrix.sync.aligned.m8n8.x4.shared.b16 {%0,%1,%2,%3}, [%4];" \
        : "=r"((r)[0]), "=r"((r)[1]), "=r"((r)[2]), "=r"((r)[3]) : "r"(addr))

#define CP_ASYNC16(dst, src) \
    asm volatile("cp.async.ca.shared.global [%0], [%1], 16;" :: "r"(dst), "l"(src))
#define CP_COMMIT() asm volatile("cp.async.commit_group;" ::: "memory")
#define CP_WAIT(n)  asm volatile("cp.async.wait_group %0;" :: "n"(n) : "memory")

__device__ __forceinline__ void mma_bf16(float* d, const uint32_t* a,
                                         uint32_t b0, uint32_t b1) {
    asm volatile(
        "mma.sync.aligned.m16n8k16.row.col.f32.bf16.bf16.f32 "
        "{%0,%1,%2,%3}, {%4,%5,%6,%7}, {%8,%9}, {%0,%1,%2,%3};"
        : "+f"(d[0]), "+f"(d[1]), "+f"(d[2]), "+f"(d[3])
        : "r"(a[0]), "r"(a[1]), "r"(a[2]), "r"(a[3]), "r"(b0), "r"(b1));
}

// ---------------- HMMA GEMM (R8 config: 128x128, 2 CTA/SM, static clamp) -------
template<int MODE, int FULLN>
__global__ __launch_bounds__(256, 2)
void gemm_mma(const float* __restrict__ A,
              const __nv_bfloat16* __restrict__ Bh,
              const __nv_bfloat16* __restrict__ Bl,
              const float* __restrict__ bias,
              float* __restrict__ C, int M, int N) {
    extern __shared__ __align__(128) char smem[];
    const uint32_t sb = smem_u32(smem);
    const int tid = threadIdx.x;
    const int wid = tid >> 5;
    const int lane = tid & 31;
    const int m0 = blockIdx.y * 128;
    const int n0 = blockIdx.x * 128;
    const int wr = wid & 3;
    const int wc = wid >> 2;

    constexpr int RB = 48;
    constexpr int STG = 128 * RB;
    const uint32_t offAh = 0, offAl = 2 * STG, offBh = 4 * STG, offBl = 6 * STG;

    int nbLim = 4;
    if (!FULLN) {
        const int rem = N - n0 - wc * 64;
        nbLim = rem >= 64 ? 4 : (rem <= 0 ? 0 : (rem + 15) >> 4);
    }

    float acc[2][8][4];
#pragma unroll
    for (int i = 0; i < 2; ++i)
#pragma unroll
        for (int j = 0; j < 8; ++j)
#pragma unroll
            for (int k = 0; k < 4; ++k) acc[i][j][k] = 0.f;

    float4 pa[2];
    const int brow = tid >> 1;
    const int bcol = (tid & 1) * 16;
    const __nv_bfloat16* bSrcH = Bh + (size_t)(n0 + brow) * DDIM + (tid & 1) * 8;
    const __nv_bfloat16* bSrcL = Bl + (size_t)(n0 + brow) * DDIM + (tid & 1) * 8;
    const uint32_t bDstOff = brow * RB + bcol;

#define ISSUE_B(c, s) do { \
    CP_ASYNC16(sb + offBh + (s) * STG + bDstOff, bSrcH + (c) * 16); \
    CP_ASYNC16(sb + offBl + (s) * STG + bDstOff, bSrcL + (c) * 16); \
    CP_COMMIT(); } while (0)

#define LOAD_A(c) do { \
    _Pragma("unroll") \
    for (int i = 0; i < 2; ++i) { \
        const int slot = tid + i * 256; \
        const int r = slot >> 2, qq = slot & 3; \
        if (m0 + r < M) \
            pa[i] = *reinterpret_cast<const float4*>(A + (size_t)(m0 + r) * DDIM + (c) * 16 + qq * 4); \
        else pa[i] = make_float4(0.f, 0.f, 0.f, 0.f); \
    } } while (0)

#define STORE_A(s) do { \
    _Pragma("unroll") \
    for (int i = 0; i < 2; ++i) { \
        const int slot = tid + i * 256; \
        const int r = slot >> 2, qq = slot & 3; \
        __nv_bfloat16 h0 = __float2bfloat16(pa[i].x); \
        __nv_bfloat16 h1 = __float2bfloat16(pa[i].y); \
        __nv_bfloat16 h2 = __float2bfloat16(pa[i].z); \
        __nv_bfloat16 h3 = __float2bfloat16(pa[i].w); \
        uint2 hv = make_uint2(pack_bf16(h0, h1), pack_bf16(h2, h3)); \
        uint2 lv = make_uint2( \
            pack_bf16(__float2bfloat16(pa[i].x - __bfloat162float(h0)), \
                      __float2bfloat16(pa[i].y - __bfloat162float(h1))), \
            pack_bf16(__float2bfloat16(pa[i].z - __bfloat162float(h2)), \
                      __float2bfloat16(pa[i].w - __bfloat162float(h3)))); \
        *reinterpret_cast<uint2*>(smem + offAh + (s) * STG + r * RB + qq * 8) = hv; \
        *reinterpret_cast<uint2*>(smem + offAl + (s) * STG + r * RB + qq * 8) = lv; \
    } } while (0)

    ISSUE_B(0, 0);
    LOAD_A(0);

    const uint32_t lmA = (wr * 32 + (lane & 15)) * RB + (lane >> 4) * 16;
    const uint32_t lmB = (wc * 64 + (lane & 15)) * RB + (lane >> 4) * 16;

    for (int c = 0; c < 16; ++c) {
        const int s = c & 1;
        STORE_A(s);
        if (c < 15) { ISSUE_B(c + 1, s ^ 1); CP_WAIT(1); }
        else        { CP_WAIT(0); }
        __syncthreads();
        if (c < 15) LOAD_A(c + 1);

        uint32_t ah[2][4], al[2][4];
#pragma unroll
        for (int mr = 0; mr < 2; ++mr) {
            LDSM4(ah[mr], sb + offAh + s * STG + lmA + mr * 16 * RB);
            LDSM4(al[mr], sb + offAl + s * STG + lmA + mr * 16 * RB);
        }
#pragma unroll
        for (int nb = 0; nb < 4; ++nb) {
            if (!FULLN && nb >= nbLim) break;
            uint32_t bh[4], bl[4];
            LDSM4(bh, sb + offBh + s * STG + lmB + nb * 16 * RB);
            LDSM4(bl, sb + offBl + s * STG + lmB + nb * 16 * RB);
#pragma unroll
            for (int mr = 0; mr < 2; ++mr) {
                mma_bf16(acc[mr][nb * 2 + 0], ah[mr], bh[0], bh[2]);
                mma_bf16(acc[mr][nb * 2 + 1], ah[mr], bh[1], bh[3]);
                mma_bf16(acc[mr][nb * 2 + 0], ah[mr], bl[0], bl[2]);
                mma_bf16(acc[mr][nb * 2 + 1], ah[mr], bl[1], bl[3]);
                mma_bf16(acc[mr][nb * 2 + 0], al[mr], bh[0], bh[2]);
                mma_bf16(acc[mr][nb * 2 + 1], al[mr], bh[1], bh[3]);
            }
        }
        __syncthreads();
    }

    // ---- epilogue ----
#pragma unroll
    for (int mr = 0; mr < 2; ++mr) {
        const int r0 = m0 + wr * 32 + mr * 16 + (lane >> 2);
#pragma unroll
        for (int f = 0; f < 8; ++f) {
            const int col = n0 + wc * 64 + f * 8 + (lane & 3) * 2;
            if (col >= N) continue;
            const float b0 = bias[col], b1 = bias[col + 1];
#pragma unroll
            for (int h = 0; h < 2; ++h) {
                const int row = r0 + h * 8;
                if (row >= M) continue;
                float x0 = acc[mr][f][h * 2 + 0] + b0;
                float x1 = acc[mr][f][h * 2 + 1] + b1;
                if (MODE == 1) { x0 = gelu_exact(x0); x1 = gelu_exact(x1); }
                *reinterpret_cast<float2*>(C + (size_t)row * N + col) = make_float2(x0, x1);
            }
        }
    }
#undef ISSUE_B
#undef LOAD_A
#undef STORE_A
}

// ---------------- weight transpose + bf16 split (once per launch) -------------
__global__ __launch_bounds__(256)
void convert_weights(const float* __restrict__ Wv, const float* __restrict__ Wo,
                     const float* __restrict__ W1, const float* __restrict__ W2,
                     const float* __restrict__ Woff, const float* __restrict__ Wattn,
                     const float* __restrict__ boff, const float* __restrict__ battn) {
    const int b = blockIdx.x;
    const int k = threadIdx.x;
    if (b == 1168) {
        if (k < 96) g_boa[k] = boff[k];
        else if (k < 144) g_boa[k] = battn[k - 96];
        return;
    }
    const float* W; __nv_bfloat16* oh; __nv_bfloat16* ol; int n, nout, N;
    if (b < 256)       { W = Wv; oh = g_bv_h; ol = g_bv_l; n = b;        nout = n; N = 256; }
    else if (b < 512)  { W = Wo; oh = g_bo_h; ol = g_bo_l; n = b - 256;  nout = n; N = 256; }
    else if (b < 768)  { W = W1; oh = g_b1_h; ol = g_b1_l; n = b - 512;  nout = n; N = 256; }
    else if (b < 1024) { W = W2; oh = g_b2_h; ol = g_b2_l; n = b - 768;  nout = n; N = 256; }
    else {
        nout = b - 1024;  // 0..143
        oh = g_boa_h; ol = g_boa_l;
        if (nout < 96) { W = Woff;  n = nout;      N = 96; }
        else           { W = Wattn; n = nout - 96; N = 48; }
    }
    const float x = W[(size_t)k * N + n];
    const __nv_bfloat16 h = __float2bfloat16(x);
    const __nv_bfloat16 l = __float2bfloat16(x - __bfloat162float(h));
    oh[(size_t)nout * DDIM + k] = h;
    ol[(size_t)nout * DDIM + k] = l;
}

// ---------------- MSDA sampling v3: metadata lanes + shuffle-broadcast --------
// One warp per (query, head). Metadata lanes pc<24 own (p=pc>>2, corner=pc&3):
// compute bilinear weight + spatial offset ONCE; gather loop broadcasts via shfl.
__global__ __launch_bounds__(256)
void msda_sample_kernel(const float* __restrict__ oa, const float* __restrict__ v,
                        const float* __restrict__ ref, const int* __restrict__ ss,
                        float* __restrict__ out) {
    const int q = blockIdx.x;
    const int h = threadIdx.x >> 5;
    const int lane = threadIdx.x & 31;
    const int corner = lane >> 3;       // gather role: corner 0..3
    const int cg = lane & 7;            // gather role: channel group (float4)

    const int H = ss[0];
    const int W = ss[1];

    const float bx = __ldg(ref + q * 2 + 0) * (float)W - 0.5f;
    const float by = __ldg(ref + q * 2 + 1) * (float)H - 0.5f;

    const float* qa = oa + (size_t)q * 144;

    // ---- metadata role: lane pc<24 owns (p = pc>>2, c_m = pc&3) ----
    const int p_m = lane >> 2;          // 0..7 (6,7 dummy)
    const int c_m = lane & 3;
    const bool metaValid = (p_m < 6);

    // lane-parallel softmax over p (padded to 8 with -inf / 0)
    float lg_own = metaValid ? __ldg(qa + 96 + h * 6 + p_m) : -1e30f;
    float mx = lg_own;
#pragma unroll
    for (int o = 4; o <= 16; o <<= 1)
        mx = fmaxf(mx, __shfl_xor_sync(0xffffffffu, mx, o));
    float e = metaValid ? __expf(lg_own - mx) : 0.f;
    float sum = e;
#pragma unroll
    for (int o = 4; o <= 16; o <<= 1)
        sum += __shfl_xor_sync(0xffffffffu, sum, o);
    const float a_own = e / sum;

    // per-(p,corner) bilinear weight + spatial offset (computed once, not 8x)
    const int pp = metaValid ? p_m : 0;
    const float ox = __ldg(qa + h * 12 + pp * 2 + 0);
    const float oy = __ldg(qa + h * 12 + pp * 2 + 1);
    const float lx = bx + ox;
    const float ly = by + oy;
    const float x0f = floorf(lx);
    const float y0f = floorf(ly);
    const float fx = lx - x0f;
    const float fy = ly - y0f;
    const int dxm = c_m & 1;
    const int dym = c_m >> 1;
    const int xi = (int)x0f + dxm;
    const int yi = (int)y0f + dym;
    const float wx = dxm ? fx : 1.f - fx;
    const float wy = dym ? fy : 1.f - fy;
    const bool valid = metaValid & (xi >= 0) & (xi < W) & (yi >= 0) & (yi < H);
    const float wv = valid ? a_own * wx * wy : 0.f;
    const uint32_t xc = (uint32_t)min(max(xi, 0), W - 1);
    const uint32_t yc = (uint32_t)min(max(yi, 0), H - 1);
    const uint32_t off_own = (yc * (uint32_t)W + xc) * 64u;   // float4 units

    // ---- gather role: all 32 lanes, 6 iterations ----
    const float4* vh = reinterpret_cast<const float4*>(v) + (h * 8 + cg);
    float4 acc = make_float4(0.f, 0.f, 0.f, 0.f);

#pragma unroll
    for (int p = 0; p < 6; ++p) {
        const int src = p * 4 + corner;
        const uint32_t off = __shfl_sync(0xffffffffu, off_own, src);
        const float w = __shfl_sync(0xffffffffu, wv, src);
        const float4 val = __ldg(vh + off);
        acc.x += w * val.x;
        acc.y += w * val.y;
        acc.z += w * val.z;
        acc.w += w * val.w;
    }

#pragma unroll
    for (int o = 8; o <= 16; o <<= 1) {
        acc.x += __shfl_xor_sync(0xffffffffu, acc.x, o);
        acc.y += __shfl_xor_sync(0xffffffffu, acc.y, o);
        acc.z += __shfl_xor_sync(0xffffffffu, acc.z, o);
        acc.w += __shfl_xor_sync(0xffffffffu, acc.w, o);
    }
    if (lane < 8)
        *reinterpret_cast<float4*>(out + (size_t)q * DDIM + h * 32 + cg * 4) = acc;
}

// ---------------- fused residual + LayerNorm -----------------------------------
__global__ __launch_bounds__(256)
void ln_kernel(const float* __restrict__ x, const float* __restrict__ res,
               const float* __restrict__ g, const float* __restrict__ b,
               float* __restrict__ out) {
    const int row = blockIdx.x;
    const int tid = threadIdx.x;
    const float v = x[(size_t)row * DDIM + tid] + res[(size_t)row * DDIM + tid];

    float s = v, s2 = v * v;
#pragma unroll
    for (int o = 16; o; o >>= 1) {
        s  += __shfl_xor_sync(0xffffffffu, s, o);
        s2 += __shfl_xor_sync(0xffffffffu, s2, o);
    }
    __shared__ float sh[16];
    const int w = tid >> 5, lane = tid & 31;
    if (lane == 0) { sh[w] = s; sh[w + 8] = s2; }
    __syncthreads();
    if (tid == 0) {
        float a = 0.f, c = 0.f;
#pragma unroll
        for (int i = 0; i < 8; ++i) { a += sh[i]; c += sh[i + 8]; }
        sh[0] = a; sh[8] = c;
    }
    __syncthreads();
    const float mean = sh[0] * (1.f / 256.f);
    const float var  = sh[8] * (1.f / 256.f) - mean * mean;
    const float rstd = rsqrtf(var + 1e-5f);
    out[(size_t)row * DDIM + tid] = (v - mean) * rstd * g[tid] + b[tid];
}

// ---------------- launch --------------------------------------------------------
extern "C" void kernel_launch(void* const* d_in, const int* in_sizes, int n_in,
                              void* d_out, int out_size) {
    const float* query  = (const float*)d_in[0];
    const float* value  = (const float*)d_in[1];
    const float* refp   = (const float*)d_in[2];
    const int*   ss     = (const int*)d_in[3];
    const float* W_off  = (const float*)d_in[5];
    const float* b_off  = (const float*)d_in[6];
    const float* W_attn = (const float*)d_in[7];
    const float* b_attn = (const float*)d_in[8];
    const float* W_val  = (const float*)d_in[9];
    const float* b_val  = (const float*)d_in[10];
    const float* W_out  = (const float*)d_in[11];
    const float* b_out  = (const float*)d_in[12];
    const float* ln1_g  = (const float*)d_in[13];
    const float* ln1_b  = (const float*)d_in[14];
    const float* W1     = (const float*)d_in[15];
    const float* b1     = (const float*)d_in[16];
    const float* W2     = (const float*)d_in[17];
    const float* b2     = (const float*)d_in[18];
    const float* ln2_g  = (const float*)d_in[19];
    const float* ln2_b  = (const float*)d_in[20];
    float* out = (float*)d_out;

    const int M  = in_sizes[0] / DDIM;
    const int Mv = in_sizes[1] / DDIM;

    float *pv, *poa, *pmsda, *ptmp, *py, *pboa;
    __nv_bfloat16 *bvh, *bvl, *boh, *bol, *b1h, *b1l, *b2h, *b2l, *boah, *boal;
    cudaGetSymbolAddress((void**)&pv,    g_v);
    cudaGetSymbolAddress((void**)&poa,   g_oa);
    cudaGetSymbolAddress((void**)&pmsda, g_msda);
    cudaGetSymbolAddress((void**)&ptmp,  g_tmp);
    cudaGetSymbolAddress((void**)&py,    g_y);
    cudaGetSymbolAddress((void**)&pboa,  g_boa);
    cudaGetSymbolAddress((void**)&bvh,   g_bv_h);
    cudaGetSymbolAddress((void**)&bvl,   g_bv_l);
    cudaGetSymbolAddress((void**)&boh,   g_bo_h);
    cudaGetSymbolAddress((void**)&bol,   g_bo_l);
    cudaGetSymbolAddress((void**)&b1h,   g_b1_h);
    cudaGetSymbolAddress((void**)&b1l,   g_b1_l);
    cudaGetSymbolAddress((void**)&b2h,   g_b2_h);
    cudaGetSymbolAddress((void**)&b2l,   g_b2_l);
    cudaGetSymbolAddress((void**)&boah,  g_boa_h);
    cudaGetSymbolAddress((void**)&boal,  g_boa_l);

    const int SMEM = 8 * 128 * 48;  // 49152 bytes
    cudaFuncSetAttribute((gemm_mma<0, 1>), cudaFuncAttributeMaxDynamicSharedMemorySize, SMEM);
    cudaFuncSetAttribute((gemm_mma<1, 1>), cudaFuncAttributeMaxDynamicSharedMemorySize, SMEM);
    cudaFuncSetAttribute((gemm_mma<0, 0>), cudaFuncAttributeMaxDynamicSharedMemorySize, SMEM);

    const int gM  = (M + 127) / 128;
    const int gMv = (Mv + 127) / 128;

    // 0) weights -> transposed bf16 hi/lo
    convert_weights<<<1169, 256>>>(W_val, W_out, W1, W2, W_off, W_attn, b_off, b_attn);
    // 1) value projection
    gemm_mma<0, 1><<<dim3(2, gMv), 256, SMEM>>>(value, bvh, bvl, b_val, pv, Mv, DDIM);
    // 2) fused offsets+attn logits GEMM (N=144, statically clamped)
    gemm_mma<0, 0><<<dim3(2, gM), 256, SMEM>>>(query, boah, boal, pboa, poa, M, 144);
    // 3) deformable sampling
    msda_sample_kernel<<<M, 256>>>(poa, pv, refp, ss, pmsda);
    // 4) output projection + residual + LN1
    gemm_mma<0, 1><<<dim3(2, gM), 256, SMEM>>>(pmsda, boh, bol, b_out, ptmp, M, DDIM);
    ln_kernel<<<M, 256>>>(ptmp, query, ln1_g, ln1_b, py);
    // 5) FFN
    gemm_mma<1, 1><<<dim3(2, gM), 256, SMEM>>>(py, b1h, b1l, b1, ptmp, M, DDIM);
    gemm_mma<0, 1><<<dim3(2, gM), 256, SMEM>>>(ptmp, b2h, b2l, b2, pmsda, M, DDIM);
    ln_kernel<<<M, 256>>>(pmsda, py, ln2_g, ln2_b, out);
}

// round 11
// speedup vs baseline: 1.3515x; 1.2354x over previous
#include <cuda_runtime.h>
#include <cuda_fp16.h>
#include <math.h>
#include <stdint.h>

#define DDIM 256
#define NQMAX 40000

// ---------------- scratch (device globals; zero-initialized, no allocation) --
__device__ __align__(16) float g_v   [NQMAX * DDIM];
__device__ __align__(16) float g_oa  [NQMAX * 144];
__device__ __align__(16) float g_msda[NQMAX * DDIM];
__device__ __align__(16) float g_tmp [NQMAX * DDIM];
__device__ __align__(16) float g_y   [NQMAX * DDIM];

// transposed + fp16-split weights: [N][K=256]   (oa padded to 256 rows, zeros)
__device__ __align__(16) __half g_bv_h[DDIM * DDIM];
__device__ __align__(16) __half g_bv_l[DDIM * DDIM];
__device__ __align__(16) __half g_bo_h[DDIM * DDIM];
__device__ __align__(16) __half g_bo_l[DDIM * DDIM];
__device__ __align__(16) __half g_b1_h[DDIM * DDIM];
__device__ __align__(16) __half g_b1_l[DDIM * DDIM];
__device__ __align__(16) __half g_b2_h[DDIM * DDIM];
__device__ __align__(16) __half g_b2_l[DDIM * DDIM];
__device__ __align__(16) __half g_boa_h[DDIM * DDIM];
__device__ __align__(16) __half g_boa_l[DDIM * DDIM];
__device__ __align__(16) float g_boa[144];

// ---------------- helpers ------------------------------------------------------
__device__ __forceinline__ uint32_t smem_u32(const void* p) {
    uint32_t a;
    asm("{ .reg .u64 t; cvta.to.shared.u64 t, %1; cvt.u32.u64 %0, t; }" : "=r"(a) : "l"(p));
    return a;
}

__device__ __forceinline__ uint32_t pack_h2(__half x, __half y) {
    __half2 t(x, y);
    return *reinterpret_cast<uint32_t*>(&t);
}

__device__ __forceinline__ float gelu_exact(float x) {
    return 0.5f * x * (1.0f + erff(x * 0.70710678118654752f));
}

#define LDSM4(r, addr) \
    asm volatile("ldmatrix.sync.aligned.m8n8.x4.shared.b16 {%0,%1,%2,%3}, [%4];" \
        : "=r"((r)[0]), "=r"((r)[1]), "=r"((r)[2]), "=r"((r)[3]) : "r"(addr))

#define CP_ASYNC16(dst, src) \
    asm volatile("cp.async.ca.shared.global [%0], [%1], 16;" :: "r"(dst), "l"(src))
#define CP_COMMIT() asm volatile("cp.async.commit_group;" ::: "memory")
#define CP_WAIT(n)  asm volatile("cp.async.wait_group %0;" :: "n"(n) : "memory")

__device__ __forceinline__ void mma_f16(float* d, const uint32_t* a,
                                        uint32_t b0, uint32_t b1) {
    asm volatile(
        "mma.sync.aligned.m16n8k16.row.col.f32.f16.f16.f32 "
        "{%0,%1,%2,%3}, {%4,%5,%6,%7}, {%8,%9}, {%0,%1,%2,%3};"
        : "+f"(d[0]), "+f"(d[1]), "+f"(d[2]), "+f"(d[3])
        : "r"(a[0]), "r"(a[1]), "r"(a[2]), "r"(a[3]), "r"(b0), "r"(b1));
}

// ---------------- HMMA GEMM v6: fp16 2-term (A hi, B hi+lo) --------------------
// C = A[M][256] @ B^T + bias.  CTA tile 128x128, 8 warps (4x2), BK=16.
// MODE 0: +bias; MODE 1: +bias then exact GELU.
// FULLN=0: clamp warp's nb range via unrolled break (oa GEMM, N=144).
template<int MODE, int FULLN>
__global__ __launch_bounds__(256, 2)
void gemm_mma(const float* __restrict__ A,
              const __half* __restrict__ Bh,
              const __half* __restrict__ Bl,
              const float* __restrict__ bias,
              float* __restrict__ C, int M, int N) {
    extern __shared__ __align__(128) char smem[];
    const uint32_t sb = smem_u32(smem);
    const int tid = threadIdx.x;
    const int wid = tid >> 5;
    const int lane = tid & 31;
    const int m0 = blockIdx.y * 128;
    const int n0 = blockIdx.x * 128;
    const int wr = wid & 3;
    const int wc = wid >> 2;

    constexpr int RB = 48;         // smem row bytes (32 data + 16 pad)
    constexpr int STG = 128 * RB;  // 6144 bytes per buffer
    // layout: A[2 bufs] | Bh[2 bufs] | Bl[2 bufs]  = 6*STG = 36864 B
    const uint32_t offA = 0, offBh = 2 * STG, offBl = 4 * STG;

    int nbLim = 4;
    if (!FULLN) {
        const int rem = N - n0 - wc * 64;
        nbLim = rem >= 64 ? 4 : (rem <= 0 ? 0 : (rem + 15) >> 4);
    }

    float acc[2][8][4];
#pragma unroll
    for (int i = 0; i < 2; ++i)
#pragma unroll
        for (int j = 0; j < 8; ++j)
#pragma unroll
            for (int k = 0; k < 4; ++k) acc[i][j][k] = 0.f;

    float4 pa[2];
    const int brow = tid >> 1;
    const int bcol = (tid & 1) * 16;
    const __half* bSrcH = Bh + (size_t)(n0 + brow) * DDIM + (tid & 1) * 8;
    const __half* bSrcL = Bl + (size_t)(n0 + brow) * DDIM + (tid & 1) * 8;
    const uint32_t bDstOff = brow * RB + bcol;

#define ISSUE_B(c, s) do { \
    CP_ASYNC16(sb + offBh + (s) * STG + bDstOff, bSrcH + (c) * 16); \
    CP_ASYNC16(sb + offBl + (s) * STG + bDstOff, bSrcL + (c) * 16); \
    CP_COMMIT(); } while (0)

#define LOAD_A(c) do { \
    _Pragma("unroll") \
    for (int i = 0; i < 2; ++i) { \
        const int slot = tid + i * 256; \
        const int r = slot >> 2, qq = slot & 3; \
        if (m0 + r < M) \
            pa[i] = *reinterpret_cast<const float4*>(A + (size_t)(m0 + r) * DDIM + (c) * 16 + qq * 4); \
        else pa[i] = make_float4(0.f, 0.f, 0.f, 0.f); \
    } } while (0)

#define STORE_A(s) do { \
    _Pragma("unroll") \
    for (int i = 0; i < 2; ++i) { \
        const int slot = tid + i * 256; \
        const int r = slot >> 2, qq = slot & 3; \
        uint2 hv = make_uint2( \
            pack_h2(__float2half(pa[i].x), __float2half(pa[i].y)), \
            pack_h2(__float2half(pa[i].z), __float2half(pa[i].w))); \
        *reinterpret_cast<uint2*>(smem + offA + (s) * STG + r * RB + qq * 8) = hv; \
    } } while (0)

    ISSUE_B(0, 0);
    LOAD_A(0);

    const uint32_t lmA = (wr * 32 + (lane & 15)) * RB + (lane >> 4) * 16;
    const uint32_t lmB = (wc * 64 + (lane & 15)) * RB + (lane >> 4) * 16;

    for (int c = 0; c < 16; ++c) {
        const int s = c & 1;
        STORE_A(s);
        if (c < 15) { ISSUE_B(c + 1, s ^ 1); CP_WAIT(1); }
        else        { CP_WAIT(0); }
        __syncthreads();
        if (c < 15) LOAD_A(c + 1);

        uint32_t ah[2][4];
#pragma unroll
        for (int mr = 0; mr < 2; ++mr)
            LDSM4(ah[mr], sb + offA + s * STG + lmA + mr * 16 * RB);

#pragma unroll
        for (int nb = 0; nb < 4; ++nb) {
            if (!FULLN && nb >= nbLim) break;
            uint32_t bh[4], bl[4];
            LDSM4(bh, sb + offBh + s * STG + lmB + nb * 16 * RB);
            LDSM4(bl, sb + offBl + s * STG + lmB + nb * 16 * RB);
#pragma unroll
            for (int mr = 0; mr < 2; ++mr) {
                mma_f16(acc[mr][nb * 2 + 0], ah[mr], bh[0], bh[2]);
                mma_f16(acc[mr][nb * 2 + 1], ah[mr], bh[1], bh[3]);
                mma_f16(acc[mr][nb * 2 + 0], ah[mr], bl[0], bl[2]);
                mma_f16(acc[mr][nb * 2 + 1], ah[mr], bl[1], bl[3]);
            }
        }
        __syncthreads();
    }

    // ---- epilogue ----
#pragma unroll
    for (int mr = 0; mr < 2; ++mr) {
        const int r0 = m0 + wr * 32 + mr * 16 + (lane >> 2);
#pragma unroll
        for (int f = 0; f < 8; ++f) {
            const int col = n0 + wc * 64 + f * 8 + (lane & 3) * 2;
            if (col >= N) continue;
            const float b0 = bias[col], b1 = bias[col + 1];
#pragma unroll
            for (int h = 0; h < 2; ++h) {
                const int row = r0 + h * 8;
                if (row >= M) continue;
                float x0 = acc[mr][f][h * 2 + 0] + b0;
                float x1 = acc[mr][f][h * 2 + 1] + b1;
                if (MODE == 1) { x0 = gelu_exact(x0); x1 = gelu_exact(x1); }
                *reinterpret_cast<float2*>(C + (size_t)row * N + col) = make_float2(x0, x1);
            }
        }
    }
#undef ISSUE_B
#undef LOAD_A
#undef STORE_A
}

// ---------------- weight transpose + fp16 split (once per launch) -------------
__global__ __launch_bounds__(256)
void convert_weights(const float* __restrict__ Wv, const float* __restrict__ Wo,
                     const float* __restrict__ W1, const float* __restrict__ W2,
                     const float* __restrict__ Woff, const float* __restrict__ Wattn,
                     const float* __restrict__ boff, const float* __restrict__ battn) {
    const int b = blockIdx.x;
    const int k = threadIdx.x;
    if (b == 1168) {
        if (k < 96) g_boa[k] = boff[k];
        else if (k < 144) g_boa[k] = battn[k - 96];
        return;
    }
    const float* W; __half* oh; __half* ol; int n, nout, N;
    if (b < 256)       { W = Wv; oh = g_bv_h; ol = g_bv_l; n = b;        nout = n; N = 256; }
    else if (b < 512)  { W = Wo; oh = g_bo_h; ol = g_bo_l; n = b - 256;  nout = n; N = 256; }
    else if (b < 768)  { W = W1; oh = g_b1_h; ol = g_b1_l; n = b - 512;  nout = n; N = 256; }
    else if (b < 1024) { W = W2; oh = g_b2_h; ol = g_b2_l; n = b - 768;  nout = n; N = 256; }
    else {
        nout = b - 1024;  // 0..143
        oh = g_boa_h; ol = g_boa_l;
        if (nout < 96) { W = Woff;  n = nout;      N = 96; }
        else           { W = Wattn; n = nout - 96; N = 48; }
    }
    const float x = W[(size_t)k * N + n];
    const __half h = __float2half(x);
    const __half l = __float2half(x - __half2float(h));
    oh[(size_t)nout * DDIM + k] = h;
    ol[(size_t)nout * DDIM + k] = l;
}

// ---------------- MSDA sampling v3: metadata lanes + shuffle-broadcast --------
__global__ __launch_bounds__(256)
void msda_sample_kernel(const float* __restrict__ oa, const float* __restrict__ v,
                        const float* __restrict__ ref, const int* __restrict__ ss,
                        float* __restrict__ out) {
    const int q = blockIdx.x;
    const int h = threadIdx.x >> 5;
    const int lane = threadIdx.x & 31;
    const int corner = lane >> 3;
    const int cg = lane & 7;

    const int H = ss[0];
    const int W = ss[1];

    const float bx = __ldg(ref + q * 2 + 0) * (float)W - 0.5f;
    const float by = __ldg(ref + q * 2 + 1) * (float)H - 0.5f;

    const float* qa = oa + (size_t)q * 144;

    const int p_m = lane >> 2;
    const int c_m = lane & 3;
    const bool metaValid = (p_m < 6);

    float lg_own = metaValid ? __ldg(qa + 96 + h * 6 + p_m) : -1e30f;
    float mx = lg_own;
#pragma unroll
    for (int o = 4; o <= 16; o <<= 1)
        mx = fmaxf(mx, __shfl_xor_sync(0xffffffffu, mx, o));
    float e = metaValid ? __expf(lg_own - mx) : 0.f;
    float sum = e;
#pragma unroll
    for (int o = 4; o <= 16; o <<= 1)
        sum += __shfl_xor_sync(0xffffffffu, sum, o);
    const float a_own = e / sum;

    const int pp = metaValid ? p_m : 0;
    const float ox = __ldg(qa + h * 12 + pp * 2 + 0);
    const float oy = __ldg(qa + h * 12 + pp * 2 + 1);
    const float lx = bx + ox;
    const float ly = by + oy;
    const float x0f = floorf(lx);
    const float y0f = floorf(ly);
    const float fx = lx - x0f;
    const float fy = ly - y0f;
    const int dxm = c_m & 1;
    const int dym = c_m >> 1;
    const int xi = (int)x0f + dxm;
    const int yi = (int)y0f + dym;
    const float wx = dxm ? fx : 1.f - fx;
    const float wy = dym ? fy : 1.f - fy;
    const bool valid = metaValid & (xi >= 0) & (xi < W) & (yi >= 0) & (yi < H);
    const float wv = valid ? a_own * wx * wy : 0.f;
    const uint32_t xc = (uint32_t)min(max(xi, 0), W - 1);
    const uint32_t yc = (uint32_t)min(max(yi, 0), H - 1);
    const uint32_t off_own = (yc * (uint32_t)W + xc) * 64u;

    const float4* vh = reinterpret_cast<const float4*>(v) + (h * 8 + cg);
    float4 acc = make_float4(0.f, 0.f, 0.f, 0.f);

#pragma unroll
    for (int p = 0; p < 6; ++p) {
        const int src = p * 4 + corner;
        const uint32_t off = __shfl_sync(0xffffffffu, off_own, src);
        const float w = __shfl_sync(0xffffffffu, wv, src);
        const float4 val = __ldg(vh + off);
        acc.x += w * val.x;
        acc.y += w * val.y;
        acc.z += w * val.z;
        acc.w += w * val.w;
    }

#pragma unroll
    for (int o = 8; o <= 16; o <<= 1) {
        acc.x += __shfl_xor_sync(0xffffffffu, acc.x, o);
        acc.y += __shfl_xor_sync(0xffffffffu, acc.y, o);
        acc.z += __shfl_xor_sync(0xffffffffu, acc.z, o);
        acc.w += __shfl_xor_sync(0xffffffffu, acc.w, o);
    }
    if (lane < 8)
        *reinterpret_cast<float4*>(out + (size_t)q * DDIM + h * 32 + cg * 4) = acc;
}

// ---------------- fused residual + LayerNorm: one warp per row -----------------
// block = 256 threads = 8 warps = 8 rows. Lane owns 8 contiguous channels.
__global__ __launch_bounds__(256)
void ln_kernel(const float* __restrict__ x, const float* __restrict__ res,
               const float* __restrict__ g, const float* __restrict__ b,
               float* __restrict__ out, int M) {
    const int row = blockIdx.x * 8 + (threadIdx.x >> 5);
    if (row >= M) return;
    const int lane = threadIdx.x & 31;
    const size_t base = (size_t)row * DDIM + lane * 8;

    float4 v0 = *reinterpret_cast<const float4*>(x + base);
    float4 v1 = *reinterpret_cast<const float4*>(x + base + 4);
    const float4 r0 = *reinterpret_cast<const float4*>(res + base);
    const float4 r1 = *reinterpret_cast<const float4*>(res + base + 4);
    v0.x += r0.x; v0.y += r0.y; v0.z += r0.z; v0.w += r0.w;
    v1.x += r1.x; v1.y += r1.y; v1.z += r1.z; v1.w += r1.w;

    float s  = v0.x + v0.y + v0.z + v0.w + v1.x + v1.y + v1.z + v1.w;
    float s2 = v0.x * v0.x + v0.y * v0.y + v0.z * v0.z + v0.w * v0.w
             + v1.x * v1.x + v1.y * v1.y + v1.z * v1.z + v1.w * v1.w;
#pragma unroll
    for (int o = 16; o; o >>= 1) {
        s  += __shfl_xor_sync(0xffffffffu, s, o);
        s2 += __shfl_xor_sync(0xffffffffu, s2, o);
    }
    const float mean = s * (1.f / 256.f);
    const float var  = s2 * (1.f / 256.f) - mean * mean;
    const float rstd = rsqrtf(var + 1e-5f);

    const float4 g0 = *reinterpret_cast<const float4*>(g + lane * 8);
    const float4 g1 = *reinterpret_cast<const float4*>(g + lane * 8 + 4);
    const float4 b0 = *reinterpret_cast<const float4*>(b + lane * 8);
    const float4 b1 = *reinterpret_cast<const float4*>(b + lane * 8 + 4);

    float4 o0, o1;
    o0.x = (v0.x - mean) * rstd * g0.x + b0.x;
    o0.y = (v0.y - mean) * rstd * g0.y + b0.y;
    o0.z = (v0.z - mean) * rstd * g0.z + b0.z;
    o0.w = (v0.w - mean) * rstd * g0.w + b0.w;
    o1.x = (v1.x - mean) * rstd * g1.x + b1.x;
    o1.y = (v1.y - mean) * rstd * g1.y + b1.y;
    o1.z = (v1.z - mean) * rstd * g1.z + b1.z;
    o1.w = (v1.w - mean) * rstd * g1.w + b1.w;
    *reinterpret_cast<float4*>(out + base)     = o0;
    *reinterpret_cast<float4*>(out + base + 4) = o1;
}

// ---------------- launch --------------------------------------------------------
extern "C" void kernel_launch(void* const* d_in, const int* in_sizes, int n_in,
                              void* d_out, int out_size) {
    const float* query  = (const float*)d_in[0];
    const float* value  = (const float*)d_in[1];
    const float* refp   = (const float*)d_in[2];
    const int*   ss     = (const int*)d_in[3];
    const float* W_off  = (const float*)d_in[5];
    const float* b_off  = (const float*)d_in[6];
    const float* W_attn = (const float*)d_in[7];
    const float* b_attn = (const float*)d_in[8];
    const float* W_val  = (const float*)d_in[9];
    const float* b_val  = (const float*)d_in[10];
    const float* W_out  = (const float*)d_in[11];
    const float* b_out  = (const float*)d_in[12];
    const float* ln1_g  = (const float*)d_in[13];
    const float* ln1_b  = (const float*)d_in[14];
    const float* W1     = (const float*)d_in[15];
    const float* b1     = (const float*)d_in[16];
    const float* W2     = (const float*)d_in[17];
    const float* b2     = (const float*)d_in[18];
    const float* ln2_g  = (const float*)d_in[19];
    const float* ln2_b  = (const float*)d_in[20];
    float* out = (float*)d_out;

    const int M  = in_sizes[0] / DDIM;
    const int Mv = in_sizes[1] / DDIM;

    float *pv, *poa, *pmsda, *ptmp, *py, *pboa;
    __half *bvh, *bvl, *boh, *bol, *b1h, *b1l, *b2h, *b2l, *boah, *boal;
    cudaGetSymbolAddress((void**)&pv,    g_v);
    cudaGetSymbolAddress((void**)&poa,   g_oa);
    cudaGetSymbolAddress((void**)&pmsda, g_msda);
    cudaGetSymbolAddress((void**)&ptmp,  g_tmp);
    cudaGetSymbolAddress((void**)&py,    g_y);
    cudaGetSymbolAddress((void**)&pboa,  g_boa);
    cudaGetSymbolAddress((void**)&bvh,   g_bv_h);
    cudaGetSymbolAddress((void**)&bvl,   g_bv_l);
    cudaGetSymbolAddress((void**)&boh,   g_bo_h);
    cudaGetSymbolAddress((void**)&bol,   g_bo_l);
    cudaGetSymbolAddress((void**)&b1h,   g_b1_h);
    cudaGetSymbolAddress((void**)&b1l,   g_b1_l);
    cudaGetSymbolAddress((void**)&b2h,   g_b2_h);
    cudaGetSymbolAddress((void**)&b2l,   g_b2_l);
    cudaGetSymbolAddress((void**)&boah,  g_boa_h);
    cudaGetSymbolAddress((void**)&boal,  g_boa_l);

    const int SMEM = 6 * 128 * 48;  // 36864 bytes
    cudaFuncSetAttribute((gemm_mma<0, 1>), cudaFuncAttributeMaxDynamicSharedMemorySize, SMEM);
    cudaFuncSetAttribute((gemm_mma<1, 1>), cudaFuncAttributeMaxDynamicSharedMemorySize, SMEM);
    cudaFuncSetAttribute((gemm_mma<0, 0>), cudaFuncAttributeMaxDynamicSharedMemorySize, SMEM);

    const int gM  = (M + 127) / 128;
    const int gMv = (Mv + 127) / 128;
    const int gLN = (M + 7) / 8;

    // 0) weights -> transposed fp16 hi/lo
    convert_weights<<<1169, 256>>>(W_val, W_out, W1, W2, W_off, W_attn, b_off, b_attn);
    // 1) value projection
    gemm_mma<0, 1><<<dim3(2, gMv), 256, SMEM>>>(value, bvh, bvl, b_val, pv, Mv, DDIM);
    // 2) fused offsets+attn logits GEMM (N=144, statically clamped)
    gemm_mma<0, 0><<<dim3(2, gM), 256, SMEM>>>(query, boah, boal, pboa, poa, M, 144);
    // 3) deformable sampling
    msda_sample_kernel<<<M, 256>>>(poa, pv, refp, ss, pmsda);
    // 4) output projection + residual + LN1
    gemm_mma<0, 1><<<dim3(2, gM), 256, SMEM>>>(pmsda, boh, bol, b_out, ptmp, M, DDIM);
    ln_kernel<<<gLN, 256>>>(ptmp, query, ln1_g, ln1_b, py, M);
    // 5) FFN
    gemm_mma<1, 1><<<dim3(2, gM), 256, SMEM>>>(py, b1h, b1l, b1, ptmp, M, DDIM);
    gemm_mma<0, 1><<<dim3(2, gM), 256, SMEM>>>(ptmp, b2h, b2l, b2, pmsda, M, DDIM);
    ln_kernel<<<gLN, 256>>>(pmsda, py, ln2_g, ln2_b, out, M);
}

// round 12
// speedup vs baseline: 1.6028x; 1.1859x over previous
#include <cuda_runtime.h>
#include <cuda_fp16.h>
#include <math.h>
#include <stdint.h>

#define DDIM 256
#define NQMAX 40000

// ---------------- scratch (device globals; zero-initialized, no allocation) --
__device__ __align__(16) float g_v   [NQMAX * DDIM];
__device__ __align__(16) float g_oa  [NQMAX * 144];
__device__ __align__(16) float g_msda[NQMAX * DDIM];
__device__ __align__(16) float g_tmp [NQMAX * DDIM];
__device__ __align__(16) float g_y   [NQMAX * DDIM];

// transposed fp16 weights: [N][K=256]   (oa padded to 256 rows, zeros)
__device__ __align__(16) __half g_bv[DDIM * DDIM];
__device__ __align__(16) __half g_bo[DDIM * DDIM];
__device__ __align__(16) __half g_b1[DDIM * DDIM];
__device__ __align__(16) __half g_b2[DDIM * DDIM];
__device__ __align__(16) __half g_boaw[DDIM * DDIM];
__device__ __align__(16) float g_boa[144];

// ---------------- helpers ------------------------------------------------------
__device__ __forceinline__ uint32_t smem_u32(const void* p) {
    uint32_t a;
    asm("{ .reg .u64 t; cvta.to.shared.u64 t, %1; cvt.u32.u64 %0, t; }" : "=r"(a) : "l"(p));
    return a;
}

__device__ __forceinline__ uint32_t pack_h2(__half x, __half y) {
    __half2 t(x, y);
    return *reinterpret_cast<uint32_t*>(&t);
}

__device__ __forceinline__ float gelu_exact(float x) {
    return 0.5f * x * (1.0f + erff(x * 0.70710678118654752f));
}

#define LDSM4(r, addr) \
    asm volatile("ldmatrix.sync.aligned.m8n8.x4.shared.b16 {%0,%1,%2,%3}, [%4];" \
        : "=r"((r)[0]), "=r"((r)[1]), "=r"((r)[2]), "=r"((r)[3]) : "r"(addr))

#define CP_ASYNC16(dst, src) \
    asm volatile("cp.async.ca.shared.global [%0], [%1], 16;" :: "r"(dst), "l"(src))
#define CP_COMMIT() asm volatile("cp.async.commit_group;" ::: "memory")
#define CP_WAIT(n)  asm volatile("cp.async.wait_group %0;" :: "n"(n) : "memory")

__device__ __forceinline__ void mma_f16(float* d, const uint32_t* a,
                                        uint32_t b0, uint32_t b1) {
    asm volatile(
        "mma.sync.aligned.m16n8k16.row.col.f32.f16.f16.f32 "
        "{%0,%1,%2,%3}, {%4,%5,%6,%7}, {%8,%9}, {%0,%1,%2,%3};"
        : "+f"(d[0]), "+f"(d[1]), "+f"(d[2]), "+f"(d[3])
        : "r"(a[0]), "r"(a[1]), "r"(a[2]), "r"(a[3]), "r"(b0), "r"(b1));
}

// ---------------- HMMA GEMM v7: single-term fp16 (A hi, B hi) ------------------
// C = A[M][256] @ B^T + bias.  CTA tile 128x128, 8 warps (4x2), BK=16.
// MODE 0: +bias; MODE 1: +bias then exact GELU.
// FULLN=0: clamp warp's nb range via unrolled break (oa GEMM, N=144).
template<int MODE, int FULLN>
__global__ __launch_bounds__(256, 2)
void gemm_mma(const float* __restrict__ A,
              const __half* __restrict__ B,
              const float* __restrict__ bias,
              float* __restrict__ C, int M, int N) {
    extern __shared__ __align__(128) char smem[];
    const uint32_t sb = smem_u32(smem);
    const int tid = threadIdx.x;
    const int wid = tid >> 5;
    const int lane = tid & 31;
    const int m0 = blockIdx.y * 128;
    const int n0 = blockIdx.x * 128;
    const int wr = wid & 3;
    const int wc = wid >> 2;

    constexpr int RB = 48;         // smem row bytes (32 data + 16 pad)
    constexpr int STG = 128 * RB;  // 6144 bytes per buffer
    // layout: A[2 bufs] | B[2 bufs] = 4*STG = 24576 B
    const uint32_t offA = 0, offB = 2 * STG;

    int nbLim = 4;
    if (!FULLN) {
        const int rem = N - n0 - wc * 64;
        nbLim = rem >= 64 ? 4 : (rem <= 0 ? 0 : (rem + 15) >> 4);
    }

    float acc[2][8][4];
#pragma unroll
    for (int i = 0; i < 2; ++i)
#pragma unroll
        for (int j = 0; j < 8; ++j)
#pragma unroll
            for (int k = 0; k < 4; ++k) acc[i][j][k] = 0.f;

    float4 pa[2];
    const int brow = tid >> 1;
    const int bcol = (tid & 1) * 16;
    const __half* bSrc = B + (size_t)(n0 + brow) * DDIM + (tid & 1) * 8;
    const uint32_t bDstOff = brow * RB + bcol;

#define ISSUE_B(c, s) do { \
    CP_ASYNC16(sb + offB + (s) * STG + bDstOff, bSrc + (c) * 16); \
    CP_COMMIT(); } while (0)

#define LOAD_A(c) do { \
    _Pragma("unroll") \
    for (int i = 0; i < 2; ++i) { \
        const int slot = tid + i * 256; \
        const int r = slot >> 2, qq = slot & 3; \
        if (m0 + r < M) \
            pa[i] = *reinterpret_cast<const float4*>(A + (size_t)(m0 + r) * DDIM + (c) * 16 + qq * 4); \
        else pa[i] = make_float4(0.f, 0.f, 0.f, 0.f); \
    } } while (0)

#define STORE_A(s) do { \
    _Pragma("unroll") \
    for (int i = 0; i < 2; ++i) { \
        const int slot = tid + i * 256; \
        const int r = slot >> 2, qq = slot & 3; \
        uint2 hv = make_uint2( \
            pack_h2(__float2half(pa[i].x), __float2half(pa[i].y)), \
            pack_h2(__float2half(pa[i].z), __float2half(pa[i].w))); \
        *reinterpret_cast<uint2*>(smem + offA + (s) * STG + r * RB + qq * 8) = hv; \
    } } while (0)

    ISSUE_B(0, 0);
    LOAD_A(0);

    const uint32_t lmA = (wr * 32 + (lane & 15)) * RB + (lane >> 4) * 16;
    const uint32_t lmB = (wc * 64 + (lane & 15)) * RB + (lane >> 4) * 16;

    for (int c = 0; c < 16; ++c) {
        const int s = c & 1;
        STORE_A(s);
        if (c < 15) { ISSUE_B(c + 1, s ^ 1); CP_WAIT(1); }
        else        { CP_WAIT(0); }
        __syncthreads();
        if (c < 15) LOAD_A(c + 1);

        uint32_t ah[2][4];
#pragma unroll
        for (int mr = 0; mr < 2; ++mr)
            LDSM4(ah[mr], sb + offA + s * STG + lmA + mr * 16 * RB);

#pragma unroll
        for (int nb = 0; nb < 4; ++nb) {
            if (!FULLN && nb >= nbLim) break;
            uint32_t bh[4];
            LDSM4(bh, sb + offB + s * STG + lmB + nb * 16 * RB);
#pragma unroll
            for (int mr = 0; mr < 2; ++mr) {
                mma_f16(acc[mr][nb * 2 + 0], ah[mr], bh[0], bh[2]);
                mma_f16(acc[mr][nb * 2 + 1], ah[mr], bh[1], bh[3]);
            }
        }
        __syncthreads();
    }

    // ---- epilogue ----
#pragma unroll
    for (int mr = 0; mr < 2; ++mr) {
        const int r0 = m0 + wr * 32 + mr * 16 + (lane >> 2);
#pragma unroll
        for (int f = 0; f < 8; ++f) {
            const int col = n0 + wc * 64 + f * 8 + (lane & 3) * 2;
            if (col >= N) continue;
            const float b0 = bias[col], b1 = bias[col + 1];
#pragma unroll
            for (int h = 0; h < 2; ++h) {
                const int row = r0 + h * 8;
                if (row >= M) continue;
                float x0 = acc[mr][f][h * 2 + 0] + b0;
                float x1 = acc[mr][f][h * 2 + 1] + b1;
                if (MODE == 1) { x0 = gelu_exact(x0); x1 = gelu_exact(x1); }
                *reinterpret_cast<float2*>(C + (size_t)row * N + col) = make_float2(x0, x1);
            }
        }
    }
#undef ISSUE_B
#undef LOAD_A
#undef STORE_A
}

// ---------------- weight transpose + fp16 convert (once per launch) -----------
__global__ __launch_bounds__(256)
void convert_weights(const float* __restrict__ Wv, const float* __restrict__ Wo,
                     const float* __restrict__ W1, const float* __restrict__ W2,
                     const float* __restrict__ Woff, const float* __restrict__ Wattn,
                     const float* __restrict__ boff, const float* __restrict__ battn) {
    const int b = blockIdx.x;
    const int k = threadIdx.x;
    if (b == 1168) {
        if (k < 96) g_boa[k] = boff[k];
        else if (k < 144) g_boa[k] = battn[k - 96];
        return;
    }
    const float* W; __half* oh; int n, nout, N;
    if (b < 256)       { W = Wv; oh = g_bv; n = b;        nout = n; N = 256; }
    else if (b < 512)  { W = Wo; oh = g_bo; n = b - 256;  nout = n; N = 256; }
    else if (b < 768)  { W = W1; oh = g_b1; n = b - 512;  nout = n; N = 256; }
    else if (b < 1024) { W = W2; oh = g_b2; n = b - 768;  nout = n; N = 256; }
    else {
        nout = b - 1024;  // 0..143
        oh = g_boaw;
        if (nout < 96) { W = Woff;  n = nout;      N = 96; }
        else           { W = Wattn; n = nout - 96; N = 48; }
    }
    oh[(size_t)nout * DDIM + k] = __float2half(W[(size_t)k * N + n]);
}

// ---------------- MSDA sampling v3: metadata lanes + shuffle-broadcast --------
__global__ __launch_bounds__(256)
void msda_sample_kernel(const float* __restrict__ oa, const float* __restrict__ v,
                        const float* __restrict__ ref, const int* __restrict__ ss,
                        float* __restrict__ out) {
    const int q = blockIdx.x;
    const int h = threadIdx.x >> 5;
    const int lane = threadIdx.x & 31;
    const int corner = lane >> 3;
    const int cg = lane & 7;

    const int H = ss[0];
    const int W = ss[1];

    const float bx = __ldg(ref + q * 2 + 0) * (float)W - 0.5f;
    const float by = __ldg(ref + q * 2 + 1) * (float)H - 0.5f;

    const float* qa = oa + (size_t)q * 144;

    const int p_m = lane >> 2;
    const int c_m = lane & 3;
    const bool metaValid = (p_m < 6);

    float lg_own = metaValid ? __ldg(qa + 96 + h * 6 + p_m) : -1e30f;
    float mx = lg_own;
#pragma unroll
    for (int o = 4; o <= 16; o <<= 1)
        mx = fmaxf(mx, __shfl_xor_sync(0xffffffffu, mx, o));
    float e = metaValid ? __expf(lg_own - mx) : 0.f;
    float sum = e;
#pragma unroll
    for (int o = 4; o <= 16; o <<= 1)
        sum += __shfl_xor_sync(0xffffffffu, sum, o);
    const float a_own = e / sum;

    const int pp = metaValid ? p_m : 0;
    const float ox = __ldg(qa + h * 12 + pp * 2 + 0);
    const float oy = __ldg(qa + h * 12 + pp * 2 + 1);
    const float lx = bx + ox;
    const float ly = by + oy;
    const float x0f = floorf(lx);
    const float y0f = floorf(ly);
    const float fx = lx - x0f;
    const float fy = ly - y0f;
    const int dxm = c_m & 1;
    const int dym = c_m >> 1;
    const int xi = (int)x0f + dxm;
    const int yi = (int)y0f + dym;
    const float wx = dxm ? fx : 1.f - fx;
    const float wy = dym ? fy : 1.f - fy;
    const bool valid = metaValid & (xi >= 0) & (xi < W) & (yi >= 0) & (yi < H);
    const float wv = valid ? a_own * wx * wy : 0.f;
    const uint32_t xc = (uint32_t)min(max(xi, 0), W - 1);
    const uint32_t yc = (uint32_t)min(max(yi, 0), H - 1);
    const uint32_t off_own = (yc * (uint32_t)W + xc) * 64u;

    const float4* vh = reinterpret_cast<const float4*>(v) + (h * 8 + cg);
    float4 acc = make_float4(0.f, 0.f, 0.f, 0.f);

#pragma unroll
    for (int p = 0; p < 6; ++p) {
        const int src = p * 4 + corner;
        const uint32_t off = __shfl_sync(0xffffffffu, off_own, src);
        const float w = __shfl_sync(0xffffffffu, wv, src);
        const float4 val = __ldg(vh + off);
        acc.x += w * val.x;
        acc.y += w * val.y;
        acc.z += w * val.z;
        acc.w += w * val.w;
    }

#pragma unroll
    for (int o = 8; o <= 16; o <<= 1) {
        acc.x += __shfl_xor_sync(0xffffffffu, acc.x, o);
        acc.y += __shfl_xor_sync(0xffffffffu, acc.y, o);
        acc.z += __shfl_xor_sync(0xffffffffu, acc.z, o);
        acc.w += __shfl_xor_sync(0xffffffffu, acc.w, o);
    }
    if (lane < 8)
        *reinterpret_cast<float4*>(out + (size_t)q * DDIM + h * 32 + cg * 4) = acc;
}

// ---------------- fused residual + LayerNorm: one warp per row -----------------
__global__ __launch_bounds__(256)
void ln_kernel(const float* __restrict__ x, const float* __restrict__ res,
               const float* __restrict__ g, const float* __restrict__ b,
               float* __restrict__ out, int M) {
    const int row = blockIdx.x * 8 + (threadIdx.x >> 5);
    if (row >= M) return;
    const int lane = threadIdx.x & 31;
    const size_t base = (size_t)row * DDIM + lane * 8;

    float4 v0 = *reinterpret_cast<const float4*>(x + base);
    float4 v1 = *reinterpret_cast<const float4*>(x + base + 4);
    const float4 r0 = *reinterpret_cast<const float4*>(res + base);
    const float4 r1 = *reinterpret_cast<const float4*>(res + base + 4);
    v0.x += r0.x; v0.y += r0.y; v0.z += r0.z; v0.w += r0.w;
    v1.x += r1.x; v1.y += r1.y; v1.z += r1.z; v1.w += r1.w;

    float s  = v0.x + v0.y + v0.z + v0.w + v1.x + v1.y + v1.z + v1.w;
    float s2 = v0.x * v0.x + v0.y * v0.y + v0.z * v0.z + v0.w * v0.w
             + v1.x * v1.x + v1.y * v1.y + v1.z * v1.z + v1.w * v1.w;
#pragma unroll
    for (int o = 16; o; o >>= 1) {
        s  += __shfl_xor_sync(0xffffffffu, s, o);
        s2 += __shfl_xor_sync(0xffffffffu, s2, o);
    }
    const float mean = s * (1.f / 256.f);
    const float var  = s2 * (1.f / 256.f) - mean * mean;
    const float rstd = rsqrtf(var + 1e-5f);

    const float4 g0 = *reinterpret_cast<const float4*>(g + lane * 8);
    const float4 g1 = *reinterpret_cast<const float4*>(g + lane * 8 + 4);
    const float4 b0 = *reinterpret_cast<const float4*>(b + lane * 8);
    const float4 b1 = *reinterpret_cast<const float4*>(b + lane * 8 + 4);

    float4 o0, o1;
    o0.x = (v0.x - mean) * rstd * g0.x + b0.x;
    o0.y = (v0.y - mean) * rstd * g0.y + b0.y;
    o0.z = (v0.z - mean) * rstd * g0.z + b0.z;
    o0.w = (v0.w - mean) * rstd * g0.w + b0.w;
    o1.x = (v1.x - mean) * rstd * g1.x + b1.x;
    o1.y = (v1.y - mean) * rstd * g1.y + b1.y;
    o1.z = (v1.z - mean) * rstd * g1.z + b1.z;
    o1.w = (v1.w - mean) * rstd * g1.w + b1.w;
    *reinterpret_cast<float4*>(out + base)     = o0;
    *reinterpret_cast<float4*>(out + base + 4) = o1;
}

// ---------------- launch --------------------------------------------------------
extern "C" void kernel_launch(void* const* d_in, const int* in_sizes, int n_in,
                              void* d_out, int out_size) {
    const float* query  = (const float*)d_in[0];
    const float* value  = (const float*)d_in[1];
    const float* refp   = (const float*)d_in[2];
    const int*   ss     = (const int*)d_in[3];
    const float* W_off  = (const float*)d_in[5];
    const float* b_off  = (const float*)d_in[6];
    const float* W_attn = (const float*)d_in[7];
    const float* b_attn = (const float*)d_in[8];
    const float* W_val  = (const float*)d_in[9];
    const float* b_val  = (const float*)d_in[10];
    const float* W_out  = (const float*)d_in[11];
    const float* b_out  = (const float*)d_in[12];
    const float* ln1_g  = (const float*)d_in[13];
    const float* ln1_b  = (const float*)d_in[14];
    const float* W1     = (const float*)d_in[15];
    const float* b1     = (const float*)d_in[16];
    const float* W2     = (const float*)d_in[17];
    const float* b2     = (const float*)d_in[18];
    const float* ln2_g  = (const float*)d_in[19];
    const float* ln2_b  = (const float*)d_in[20];
    float* out = (float*)d_out;

    const int M  = in_sizes[0] / DDIM;
    const int Mv = in_sizes[1] / DDIM;

    float *pv, *poa, *pmsda, *ptmp, *py, *pboa;
    __half *bv, *bo, *b1w, *b2w, *boaw;
    cudaGetSymbolAddress((void**)&pv,    g_v);
    cudaGetSymbolAddress((void**)&poa,   g_oa);
    cudaGetSymbolAddress((void**)&pmsda, g_msda);
    cudaGetSymbolAddress((void**)&ptmp,  g_tmp);
    cudaGetSymbolAddress((void**)&py,    g_y);
    cudaGetSymbolAddress((void**)&pboa,  g_boa);
    cudaGetSymbolAddress((void**)&bv,    g_bv);
    cudaGetSymbolAddress((void**)&bo,    g_bo);
    cudaGetSymbolAddress((void**)&b1w,   g_b1);
    cudaGetSymbolAddress((void**)&b2w,   g_b2);
    cudaGetSymbolAddress((void**)&boaw,  g_boaw);

    const int SMEM = 4 * 128 * 48;  // 24576 bytes
    cudaFuncSetAttribute((gemm_mma<0, 1>), cudaFuncAttributeMaxDynamicSharedMemorySize, SMEM);
    cudaFuncSetAttribute((gemm_mma<1, 1>), cudaFuncAttributeMaxDynamicSharedMemorySize, SMEM);
    cudaFuncSetAttribute((gemm_mma<0, 0>), cudaFuncAttributeMaxDynamicSharedMemorySize, SMEM);

    const int gM  = (M + 127) / 128;
    const int gMv = (Mv + 127) / 128;
    const int gLN = (M + 7) / 8;

    // 0) weights -> transposed fp16
    convert_weights<<<1169, 256>>>(W_val, W_out, W1, W2, W_off, W_attn, b_off, b_attn);
    // 1) value projection
    gemm_mma<0, 1><<<dim3(2, gMv), 256, SMEM>>>(value, bv, b_val, pv, Mv, DDIM);
    // 2) fused offsets+attn logits GEMM (N=144, statically clamped)
    gemm_mma<0, 0><<<dim3(2, gM), 256, SMEM>>>(query, boaw, pboa, poa, M, 144);
    // 3) deformable sampling
    msda_sample_kernel<<<M, 256>>>(poa, pv, refp, ss, pmsda);
    // 4) output projection + residual + LN1
    gemm_mma<0, 1><<<dim3(2, gM), 256, SMEM>>>(pmsda, bo, b_out, ptmp, M, DDIM);
    ln_kernel<<<gLN, 256>>>(ptmp, query, ln1_g, ln1_b, py, M);
    // 5) FFN
    gemm_mma<1, 1><<<dim3(2, gM), 256, SMEM>>>(py, b1w, b1, ptmp, M, DDIM);
    gemm_mma<0, 1><<<dim3(2, gM), 256, SMEM>>>(ptmp, b2w, b2, pmsda, M, DDIM);
    ln_kernel<<<gLN, 256>>>(pmsda, py, ln2_g, ln2_b, out, M);
}

// round 13
// speedup vs baseline: 1.6442x; 1.0259x over previous
#include <cuda_runtime.h>
#include <cuda_fp16.h>
#include <math.h>
#include <stdint.h>

#define DDIM 256
#define NQMAX 40000

// ---------------- scratch (device globals; zero-initialized, no allocation) --
__device__ __align__(16) float g_v   [NQMAX * DDIM];   // value proj (fp32, msda gathers)
__device__ __align__(16) float g_oa  [NQMAX * 144];    // offsets+logits
__device__ __align__(16) float g_tmp [NQMAX * DDIM];   // fp32 GEMM outputs (pre-LN)
__device__ __align__(16) float g_y   [NQMAX * DDIM];   // ln1 fp32 (residual for ln2)

// fp16 activation streams (GEMM A operands)
__device__ __align__(16) __half g_q16[NQMAX * DDIM];   // query
__device__ __align__(16) __half g_a16[NQMAX * DDIM];   // value input
__device__ __align__(16) __half g_m16[NQMAX * DDIM];   // msda out
__device__ __align__(16) __half g_y16[NQMAX * DDIM];   // ln1 out
__device__ __align__(16) __half g_h16[NQMAX * DDIM];   // gelu hidden

// transposed fp16 weights: [N][K=256]   (oa padded to 256 rows, zeros)
__device__ __align__(16) __half g_bv[DDIM * DDIM];
__device__ __align__(16) __half g_bo[DDIM * DDIM];
__device__ __align__(16) __half g_b1[DDIM * DDIM];
__device__ __align__(16) __half g_b2[DDIM * DDIM];
__device__ __align__(16) __half g_boaw[DDIM * DDIM];
__device__ __align__(16) float g_boa[144];

// ---------------- helpers ------------------------------------------------------
__device__ __forceinline__ uint32_t smem_u32(const void* p) {
    uint32_t a;
    asm("{ .reg .u64 t; cvta.to.shared.u64 t, %1; cvt.u32.u64 %0, t; }" : "=r"(a) : "l"(p));
    return a;
}

__device__ __forceinline__ uint32_t pack_h2(__half x, __half y) {
    __half2 t(x, y);
    return *reinterpret_cast<uint32_t*>(&t);
}

__device__ __forceinline__ float gelu_exact(float x) {
    return 0.5f * x * (1.0f + erff(x * 0.70710678118654752f));
}

#define LDSM4(r, addr) \
    asm volatile("ldmatrix.sync.aligned.m8n8.x4.shared.b16 {%0,%1,%2,%3}, [%4];" \
        : "=r"((r)[0]), "=r"((r)[1]), "=r"((r)[2]), "=r"((r)[3]) : "r"(addr))

#define CP_ASYNC16(dst, src) \
    asm volatile("cp.async.ca.shared.global [%0], [%1], 16;" :: "r"(dst), "l"(src))
#define CP_ASYNC16Z(dst, src, sz) \
    asm volatile("cp.async.ca.shared.global [%0], [%1], 16, %2;" \
                 :: "r"(dst), "l"(src), "r"(sz))
#define CP_COMMIT() asm volatile("cp.async.commit_group;" ::: "memory")
#define CP_WAIT(n)  asm volatile("cp.async.wait_group %0;" :: "n"(n) : "memory")

__device__ __forceinline__ void mma_f16(float* d, const uint32_t* a,
                                        uint32_t b0, uint32_t b1) {
    asm volatile(
        "mma.sync.aligned.m16n8k16.row.col.f32.f16.f16.f32 "
        "{%0,%1,%2,%3}, {%4,%5,%6,%7}, {%8,%9}, {%0,%1,%2,%3};"
        : "+f"(d[0]), "+f"(d[1]), "+f"(d[2]), "+f"(d[3])
        : "r"(a[0]), "r"(a[1]), "r"(a[2]), "r"(a[3]), "r"(b0), "r"(b1));
}

// ---------------- HMMA GEMM v8: fp16 A + B, pure cp.async mainloop -------------
// C = A[M][256] @ B^T + bias.  CTA tile 128x128, 8 warps (4x2), BK=16.
// MODE 0: write fp32 Cf.  MODE 1: gelu, write fp16 Ch only.
// FULLN=0: clamp warp's nb range via unrolled break (oa GEMM, N=144).
template<int MODE, int FULLN>
__global__ __launch_bounds__(256, 2)
void gemm_mma(const __half* __restrict__ A,
              const __half* __restrict__ B,
              const float* __restrict__ bias,
              float* __restrict__ Cf, __half* __restrict__ Ch,
              int M, int N) {
    extern __shared__ __align__(128) char smem[];
    const uint32_t sb = smem_u32(smem);
    const int tid = threadIdx.x;
    const int wid = tid >> 5;
    const int lane = tid & 31;
    const int m0 = blockIdx.y * 128;
    const int n0 = blockIdx.x * 128;
    const int wr = wid & 3;
    const int wc = wid >> 2;

    constexpr int RB = 48;         // smem row bytes (32 data + 16 pad)
    constexpr int STG = 128 * RB;  // 6144 bytes per buffer
    // layout: A[2 bufs] | B[2 bufs] = 4*STG = 24576 B
    const uint32_t offA = 0, offB = 2 * STG;

    int nbLim = 4;
    if (!FULLN) {
        const int rem = N - n0 - wc * 64;
        nbLim = rem >= 64 ? 4 : (rem <= 0 ? 0 : (rem + 15) >> 4);
    }

    float acc[2][8][4];
#pragma unroll
    for (int i = 0; i < 2; ++i)
#pragma unroll
        for (int j = 0; j < 8; ++j)
#pragma unroll
            for (int k = 0; k < 4; ++k) acc[i][j][k] = 0.f;

    const int row = tid >> 1;
    const int half = tid & 1;
    const uint32_t dstOff = row * RB + half * 16;
    const int arow = min(m0 + row, M - 1);
    const uint32_t aValid = (m0 + row < M) ? 16u : 0u;
    const __half* aSrc = A + (size_t)arow * DDIM + half * 8;
    const __half* bSrc = B + (size_t)(n0 + row) * DDIM + half * 8;

#define ISSUE(c, s) do { \
    CP_ASYNC16Z(sb + offA + (s) * STG + dstOff, aSrc + (c) * 16, aValid); \
    CP_ASYNC16(sb + offB + (s) * STG + dstOff, bSrc + (c) * 16); \
    CP_COMMIT(); } while (0)

    ISSUE(0, 0);

    const uint32_t lmA = (wr * 32 + (lane & 15)) * RB + (lane >> 4) * 16;
    const uint32_t lmB = (wc * 64 + (lane & 15)) * RB + (lane >> 4) * 16;

    for (int c = 0; c < 16; ++c) {
        const int s = c & 1;
        if (c < 15) { ISSUE(c + 1, s ^ 1); CP_WAIT(1); }
        else        { CP_WAIT(0); }
        __syncthreads();

        uint32_t ah[2][4];
#pragma unroll
        for (int mr = 0; mr < 2; ++mr)
            LDSM4(ah[mr], sb + offA + s * STG + lmA + mr * 16 * RB);

#pragma unroll
        for (int nb = 0; nb < 4; ++nb) {
            if (!FULLN && nb >= nbLim) break;
            uint32_t bh[4];
            LDSM4(bh, sb + offB + s * STG + lmB + nb * 16 * RB);
#pragma unroll
            for (int mr = 0; mr < 2; ++mr) {
                mma_f16(acc[mr][nb * 2 + 0], ah[mr], bh[0], bh[2]);
                mma_f16(acc[mr][nb * 2 + 1], ah[mr], bh[1], bh[3]);
            }
        }
        __syncthreads();
    }

    // ---- epilogue ----
#pragma unroll
    for (int mr = 0; mr < 2; ++mr) {
        const int r0 = m0 + wr * 32 + mr * 16 + (lane >> 2);
#pragma unroll
        for (int f = 0; f < 8; ++f) {
            const int col = n0 + wc * 64 + f * 8 + (lane & 3) * 2;
            if (col >= N) continue;
            const float b0 = bias[col], b1 = bias[col + 1];
#pragma unroll
            for (int h = 0; h < 2; ++h) {
                const int r = r0 + h * 8;
                if (r >= M) continue;
                float x0 = acc[mr][f][h * 2 + 0] + b0;
                float x1 = acc[mr][f][h * 2 + 1] + b1;
                if (MODE == 1) {
                    x0 = gelu_exact(x0); x1 = gelu_exact(x1);
                    *reinterpret_cast<uint32_t*>(Ch + (size_t)r * DDIM + col) =
                        pack_h2(__float2half(x0), __float2half(x1));
                } else {
                    *reinterpret_cast<float2*>(Cf + (size_t)r * N + col) = make_float2(x0, x1);
                }
            }
        }
    }
#undef ISSUE
}

// ---------------- fp32 -> fp16 activation convert ------------------------------
__global__ __launch_bounds__(256)
void split_act(const float* __restrict__ x, __half* __restrict__ h, int n4) {
    const int i = blockIdx.x * 256 + threadIdx.x;
    if (i >= n4) return;
    const float4 v = __ldg(reinterpret_cast<const float4*>(x) + i);
    uint2 hv = make_uint2(pack_h2(__float2half(v.x), __float2half(v.y)),
                          pack_h2(__float2half(v.z), __float2half(v.w)));
    *reinterpret_cast<uint2*>(h + (size_t)i * 4) = hv;
}

// ---------------- weight transpose + fp16 convert (once per launch) -----------
__global__ __launch_bounds__(256)
void convert_weights(const float* __restrict__ Wv, const float* __restrict__ Wo,
                     const float* __restrict__ W1, const float* __restrict__ W2,
                     const float* __restrict__ Woff, const float* __restrict__ Wattn,
                     const float* __restrict__ boff, const float* __restrict__ battn) {
    const int b = blockIdx.x;
    const int k = threadIdx.x;
    if (b == 1168) {
        if (k < 96) g_boa[k] = boff[k];
        else if (k < 144) g_boa[k] = battn[k - 96];
        return;
    }
    const float* W; __half* oh; int n, nout, N;
    if (b < 256)       { W = Wv; oh = g_bv; n = b;        nout = n; N = 256; }
    else if (b < 512)  { W = Wo; oh = g_bo; n = b - 256;  nout = n; N = 256; }
    else if (b < 768)  { W = W1; oh = g_b1; n = b - 512;  nout = n; N = 256; }
    else if (b < 1024) { W = W2; oh = g_b2; n = b - 768;  nout = n; N = 256; }
    else {
        nout = b - 1024;  // 0..143
        oh = g_boaw;
        if (nout < 96) { W = Woff;  n = nout;      N = 96; }
        else           { W = Wattn; n = nout - 96; N = 48; }
    }
    oh[(size_t)nout * DDIM + k] = __float2half(W[(size_t)k * N + n]);
}

// ---------------- MSDA sampling v3: metadata lanes + shuffle-broadcast --------
// Writes fp16 directly (value identical to later rounding).
__global__ __launch_bounds__(256)
void msda_sample_kernel(const float* __restrict__ oa, const float* __restrict__ v,
                        const float* __restrict__ ref, const int* __restrict__ ss,
                        __half* __restrict__ out) {
    const int q = blockIdx.x;
    const int h = threadIdx.x >> 5;
    const int lane = threadIdx.x & 31;
    const int corner = lane >> 3;
    const int cg = lane & 7;

    const int H = ss[0];
    const int W = ss[1];

    const float bx = __ldg(ref + q * 2 + 0) * (float)W - 0.5f;
    const float by = __ldg(ref + q * 2 + 1) * (float)H - 0.5f;

    const float* qa = oa + (size_t)q * 144;

    const int p_m = lane >> 2;
    const int c_m = lane & 3;
    const bool metaValid = (p_m < 6);

    float lg_own = metaValid ? __ldg(qa + 96 + h * 6 + p_m) : -1e30f;
    float mx = lg_own;
#pragma unroll
    for (int o = 4; o <= 16; o <<= 1)
        mx = fmaxf(mx, __shfl_xor_sync(0xffffffffu, mx, o));
    float e = metaValid ? __expf(lg_own - mx) : 0.f;
    float sum = e;
#pragma unroll
    for (int o = 4; o <= 16; o <<= 1)
        sum += __shfl_xor_sync(0xffffffffu, sum, o);
    const float a_own = e / sum;

    const int pp = metaValid ? p_m : 0;
    const float ox = __ldg(qa + h * 12 + pp * 2 + 0);
    const float oy = __ldg(qa + h * 12 + pp * 2 + 1);
    const float lx = bx + ox;
    const float ly = by + oy;
    const float x0f = floorf(lx);
    const float y0f = floorf(ly);
    const float fx = lx - x0f;
    const float fy = ly - y0f;
    const int dxm = c_m & 1;
    const int dym = c_m >> 1;
    const int xi = (int)x0f + dxm;
    const int yi = (int)y0f + dym;
    const float wx = dxm ? fx : 1.f - fx;
    const float wy = dym ? fy : 1.f - fy;
    const bool valid = metaValid & (xi >= 0) & (xi < W) & (yi >= 0) & (yi < H);
    const float wv = valid ? a_own * wx * wy : 0.f;
    const uint32_t xc = (uint32_t)min(max(xi, 0), W - 1);
    const uint32_t yc = (uint32_t)min(max(yi, 0), H - 1);
    const uint32_t off_own = (yc * (uint32_t)W + xc) * 64u;

    const float4* vh = reinterpret_cast<const float4*>(v) + (h * 8 + cg);
    float4 acc = make_float4(0.f, 0.f, 0.f, 0.f);

#pragma unroll
    for (int p = 0; p < 6; ++p) {
        const int src = p * 4 + corner;
        const uint32_t off = __shfl_sync(0xffffffffu, off_own, src);
        const float w = __shfl_sync(0xffffffffu, wv, src);
        const float4 val = __ldg(vh + off);
        acc.x += w * val.x;
        acc.y += w * val.y;
        acc.z += w * val.z;
        acc.w += w * val.w;
    }

#pragma unroll
    for (int o = 8; o <= 16; o <<= 1) {
        acc.x += __shfl_xor_sync(0xffffffffu, acc.x, o);
        acc.y += __shfl_xor_sync(0xffffffffu, acc.y, o);
        acc.z += __shfl_xor_sync(0xffffffffu, acc.z, o);
        acc.w += __shfl_xor_sync(0xffffffffu, acc.w, o);
    }
    if (lane < 8) {
        uint2 hv = make_uint2(pack_h2(__float2half(acc.x), __float2half(acc.y)),
                              pack_h2(__float2half(acc.z), __float2half(acc.w)));
        *reinterpret_cast<uint2*>(out + (size_t)q * DDIM + h * 32 + cg * 4) = hv;
    }
}

// ---------------- fused residual + LayerNorm: one warp per row -----------------
// SPLIT=1: also write fp16 copy (GEMM A operand).
template<int SPLIT>
__global__ __launch_bounds__(256)
void ln_kernel(const float* __restrict__ x, const float* __restrict__ res,
               const float* __restrict__ g, const float* __restrict__ b,
               float* __restrict__ out, __half* __restrict__ out16, int M) {
    const int row = blockIdx.x * 8 + (threadIdx.x >> 5);
    if (row >= M) return;
    const int lane = threadIdx.x & 31;
    const size_t base = (size_t)row * DDIM + lane * 8;

    float4 v0 = *reinterpret_cast<const float4*>(x + base);
    float4 v1 = *reinterpret_cast<const float4*>(x + base + 4);
    const float4 r0 = *reinterpret_cast<const float4*>(res + base);
    const float4 r1 = *reinterpret_cast<const float4*>(res + base + 4);
    v0.x += r0.x; v0.y += r0.y; v0.z += r0.z; v0.w += r0.w;
    v1.x += r1.x; v1.y += r1.y; v1.z += r1.z; v1.w += r1.w;

    float s  = v0.x + v0.y + v0.z + v0.w + v1.x + v1.y + v1.z + v1.w;
    float s2 = v0.x * v0.x + v0.y * v0.y + v0.z * v0.z + v0.w * v0.w
             + v1.x * v1.x + v1.y * v1.y + v1.z * v1.z + v1.w * v1.w;
#pragma unroll
    for (int o = 16; o; o >>= 1) {
        s  += __shfl_xor_sync(0xffffffffu, s, o);
        s2 += __shfl_xor_sync(0xffffffffu, s2, o);
    }
    const float mean = s * (1.f / 256.f);
    const float var  = s2 * (1.f / 256.f) - mean * mean;
    const float rstd = rsqrtf(var + 1e-5f);

    const float4 g0 = *reinterpret_cast<const float4*>(g + lane * 8);
    const float4 g1 = *reinterpret_cast<const float4*>(g + lane * 8 + 4);
    const float4 b0 = *reinterpret_cast<const float4*>(b + lane * 8);
    const float4 b1 = *reinterpret_cast<const float4*>(b + lane * 8 + 4);

    float4 o0, o1;
    o0.x = (v0.x - mean) * rstd * g0.x + b0.x;
    o0.y = (v0.y - mean) * rstd * g0.y + b0.y;
    o0.z = (v0.z - mean) * rstd * g0.z + b0.z;
    o0.w = (v0.w - mean) * rstd * g0.w + b0.w;
    o1.x = (v1.x - mean) * rstd * g1.x + b1.x;
    o1.y = (v1.y - mean) * rstd * g1.y + b1.y;
    o1.z = (v1.z - mean) * rstd * g1.z + b1.z;
    o1.w = (v1.w - mean) * rstd * g1.w + b1.w;
    *reinterpret_cast<float4*>(out + base)     = o0;
    *reinterpret_cast<float4*>(out + base + 4) = o1;
    if (SPLIT) {
        uint4 hv;
        hv.x = pack_h2(__float2half(o0.x), __float2half(o0.y));
        hv.y = pack_h2(__float2half(o0.z), __float2half(o0.w));
        hv.z = pack_h2(__float2half(o1.x), __float2half(o1.y));
        hv.w = pack_h2(__float2half(o1.z), __float2half(o1.w));
        *reinterpret_cast<uint4*>(out16 + base) = hv;
    }
}

// ---------------- launch --------------------------------------------------------
extern "C" void kernel_launch(void* const* d_in, const int* in_sizes, int n_in,
                              void* d_out, int out_size) {
    const float* query  = (const float*)d_in[0];
    const float* value  = (const float*)d_in[1];
    const float* refp   = (const float*)d_in[2];
    const int*   ss     = (const int*)d_in[3];
    const float* W_off  = (const float*)d_in[5];
    const float* b_off  = (const float*)d_in[6];
    const float* W_attn = (const float*)d_in[7];
    const float* b_attn = (const float*)d_in[8];
    const float* W_val  = (const float*)d_in[9];
    const float* b_val  = (const float*)d_in[10];
    const float* W_out  = (const float*)d_in[11];
    const float* b_out  = (const float*)d_in[12];
    const float* ln1_g  = (const float*)d_in[13];
    const float* ln1_b  = (const float*)d_in[14];
    const float* W1     = (const float*)d_in[15];
    const float* b1     = (const float*)d_in[16];
    const float* W2     = (const float*)d_in[17];
    const float* b2     = (const float*)d_in[18];
    const float* ln2_g  = (const float*)d_in[19];
    const float* ln2_b  = (const float*)d_in[20];
    float* out = (float*)d_out;

    const int M  = in_sizes[0] / DDIM;
    const int Mv = in_sizes[1] / DDIM;

    float *pv, *poa, *ptmp, *py, *pboa;
    __half *q16, *a16, *m16, *y16, *h16;
    __half *bv, *bo, *b1w, *b2w, *boaw;
    cudaGetSymbolAddress((void**)&pv,    g_v);
    cudaGetSymbolAddress((void**)&poa,   g_oa);
    cudaGetSymbolAddress((void**)&ptmp,  g_tmp);
    cudaGetSymbolAddress((void**)&py,    g_y);
    cudaGetSymbolAddress((void**)&pboa,  g_boa);
    cudaGetSymbolAddress((void**)&q16,   g_q16);
    cudaGetSymbolAddress((void**)&a16,   g_a16);
    cudaGetSymbolAddress((void**)&m16,   g_m16);
    cudaGetSymbolAddress((void**)&y16,   g_y16);
    cudaGetSymbolAddress((void**)&h16,   g_h16);
    cudaGetSymbolAddress((void**)&bv,    g_bv);
    cudaGetSymbolAddress((void**)&bo,    g_bo);
    cudaGetSymbolAddress((void**)&b1w,   g_b1);
    cudaGetSymbolAddress((void**)&b2w,   g_b2);
    cudaGetSymbolAddress((void**)&boaw,  g_boaw);

    const int SMEM = 4 * 128 * 48;  // 24576 bytes
    cudaFuncSetAttribute((gemm_mma<0, 1>), cudaFuncAttributeMaxDynamicSharedMemorySize, SMEM);
    cudaFuncSetAttribute((gemm_mma<1, 1>), cudaFuncAttributeMaxDynamicSharedMemorySize, SMEM);
    cudaFuncSetAttribute((gemm_mma<0, 0>), cudaFuncAttributeMaxDynamicSharedMemorySize, SMEM);

    const int gM  = (M + 127) / 128;
    const int gMv = (Mv + 127) / 128;
    const int gLN = (M + 7) / 8;

    // 0) weights -> transposed fp16; activations -> fp16
    convert_weights<<<1169, 256>>>(W_val, W_out, W1, W2, W_off, W_attn, b_off, b_attn);
    split_act<<<(M * 64 + 255) / 256, 256>>>(query, q16, M * 64);
    split_act<<<(Mv * 64 + 255) / 256, 256>>>(value, a16, Mv * 64);
    // 1) value projection
    gemm_mma<0, 1><<<dim3(2, gMv), 256, SMEM>>>(a16, bv, b_val, pv, nullptr, Mv, DDIM);
    // 2) fused offsets+attn logits GEMM (N=144, statically clamped)
    gemm_mma<0, 0><<<dim3(2, gM), 256, SMEM>>>(q16, boaw, pboa, poa, nullptr, M, 144);
    // 3) deformable sampling -> fp16
    msda_sample_kernel<<<M, 256>>>(poa, pv, refp, ss, m16);
    // 4) output projection + residual + LN1
    gemm_mma<0, 1><<<dim3(2, gM), 256, SMEM>>>(m16, bo, b_out, ptmp, nullptr, M, DDIM);
    ln_kernel<1><<<gLN, 256>>>(ptmp, query, ln1_g, ln1_b, py, y16, M);
    // 5) FFN
    gemm_mma<1, 1><<<dim3(2, gM), 256, SMEM>>>(y16, b1w, b1, nullptr, h16, M, DDIM);
    gemm_mma<0, 1><<<dim3(2, gM), 256, SMEM>>>(h16, b2w, b2, ptmp, nullptr, M, DDIM);
    ln_kernel<0><<<gLN, 256>>>(ptmp, py, ln2_g, ln2_b, out, nullptr, M);
}

// round 14
// speedup vs baseline: 1.7319x; 1.0533x over previous
#include <cuda_runtime.h>
#include <cuda_fp16.h>
#include <math.h>
#include <stdint.h>

#define DDIM 256
#define NQMAX 40000

// ---------------- scratch (device globals; zero-initialized, no allocation) --
__device__ __align__(16) float g_v   [NQMAX * DDIM];   // value proj (fp32, msda gathers)
__device__ __align__(16) float g_oa  [NQMAX * 144];    // offsets+logits
__device__ __align__(16) float g_tmp [NQMAX * DDIM];   // fp32 GEMM outputs (pre-LN)
__device__ __align__(16) float g_y   [NQMAX * DDIM];   // ln1 fp32 (residual for ln2)

// fp16 activation streams (GEMM A operands)
__device__ __align__(16) __half g_q16[NQMAX * DDIM];   // query
__device__ __align__(16) __half g_a16[NQMAX * DDIM];   // value input
__device__ __align__(16) __half g_m16[NQMAX * DDIM];   // msda out
__device__ __align__(16) __half g_y16[NQMAX * DDIM];   // ln1 out
__device__ __align__(16) __half g_h16[NQMAX * DDIM];   // gelu hidden

// transposed fp16 weights: [N][K=256]   (oa padded to 256 rows, zeros)
__device__ __align__(16) __half g_bv[DDIM * DDIM];
__device__ __align__(16) __half g_bo[DDIM * DDIM];
__device__ __align__(16) __half g_b1[DDIM * DDIM];
__device__ __align__(16) __half g_b2[DDIM * DDIM];
__device__ __align__(16) __half g_boaw[DDIM * DDIM];
__device__ __align__(16) float g_boa[144];

// ---------------- helpers ------------------------------------------------------
__device__ __forceinline__ uint32_t smem_u32(const void* p) {
    uint32_t a;
    asm("{ .reg .u64 t; cvta.to.shared.u64 t, %1; cvt.u32.u64 %0, t; }" : "=r"(a) : "l"(p));
    return a;
}

__device__ __forceinline__ uint32_t pack_h2(__half x, __half y) {
    __half2 t(x, y);
    return *reinterpret_cast<uint32_t*>(&t);
}

__device__ __forceinline__ float gelu_exact(float x) {
    return 0.5f * x * (1.0f + erff(x * 0.70710678118654752f));
}

#define LDSM4(r, addr) \
    asm volatile("ldmatrix.sync.aligned.m8n8.x4.shared.b16 {%0,%1,%2,%3}, [%4];" \
        : "=r"((r)[0]), "=r"((r)[1]), "=r"((r)[2]), "=r"((r)[3]) : "r"(addr))

#define CP_ASYNC16(dst, src) \
    asm volatile("cp.async.ca.shared.global [%0], [%1], 16;" :: "r"(dst), "l"(src))
#define CP_ASYNC16Z(dst, src, sz) \
    asm volatile("cp.async.ca.shared.global [%0], [%1], 16, %2;" \
                 :: "r"(dst), "l"(src), "r"(sz))
#define CP_COMMIT() asm volatile("cp.async.commit_group;" ::: "memory")
#define CP_WAIT(n)  asm volatile("cp.async.wait_group %0;" :: "n"(n) : "memory")

__device__ __forceinline__ void mma_f16(float* d, const uint32_t* a,
                                        uint32_t b0, uint32_t b1) {
    asm volatile(
        "mma.sync.aligned.m16n8k16.row.col.f32.f16.f16.f32 "
        "{%0,%1,%2,%3}, {%4,%5,%6,%7}, {%8,%9}, {%0,%1,%2,%3};"
        : "+f"(d[0]), "+f"(d[1]), "+f"(d[2]), "+f"(d[3])
        : "r"(a[0]), "r"(a[1]), "r"(a[2]), "r"(a[3]), "r"(b0), "r"(b1));
}

// ---------------- HMMA GEMM v9: 4-stage cp.async pipeline, single sync ---------
// C = A[M][256] @ B^T + bias.  CTA tile 128x128, 8 warps (4x2), BK=16.
// MODE 0: write fp32 Cf.  MODE 1: gelu, write fp16 Ch only.
// FULLN=0: clamp warp's nb range via unrolled break (oa GEMM, N=144).
template<int MODE, int FULLN>
__global__ __launch_bounds__(256, 2)
void gemm_mma(const __half* __restrict__ A,
              const __half* __restrict__ B,
              const float* __restrict__ bias,
              float* __restrict__ Cf, __half* __restrict__ Ch,
              int M, int N) {
    extern __shared__ __align__(128) char smem[];
    const uint32_t sb = smem_u32(smem);
    const int tid = threadIdx.x;
    const int wid = tid >> 5;
    const int lane = tid & 31;
    const int m0 = blockIdx.y * 128;
    const int n0 = blockIdx.x * 128;
    const int wr = wid & 3;
    const int wc = wid >> 2;

    constexpr int RB = 48;             // smem row bytes (32 data + 16 pad)
    constexpr int STG = 128 * RB;      // 6144 per array
    constexpr int SSTR = 2 * STG;      // 12288 per stage (A|B); 4 stages = 48KB

    int nbLim = 4;
    if (!FULLN) {
        const int rem = N - n0 - wc * 64;
        nbLim = rem >= 64 ? 4 : (rem <= 0 ? 0 : (rem + 15) >> 4);
    }

    float acc[2][8][4];
#pragma unroll
    for (int i = 0; i < 2; ++i)
#pragma unroll
        for (int j = 0; j < 8; ++j)
#pragma unroll
            for (int k = 0; k < 4; ++k) acc[i][j][k] = 0.f;

    const int row = tid >> 1;
    const int half = tid & 1;
    const uint32_t dstOff = row * RB + half * 16;
    const int arow = min(m0 + row, M - 1);
    const uint32_t aValid = (m0 + row < M) ? 16u : 0u;
    const __half* aSrc = A + (size_t)arow * DDIM + half * 8;
    const __half* bSrc = B + (size_t)(n0 + row) * DDIM + half * 8;

#define ISSUE(c) do { \
    const uint32_t base = sb + ((c) & 3) * SSTR + dstOff; \
    CP_ASYNC16Z(base,       aSrc + (c) * 16, aValid); \
    CP_ASYNC16(base + STG,  bSrc + (c) * 16); \
    CP_COMMIT(); } while (0)

    ISSUE(0);
    ISSUE(1);
    ISSUE(2);

    const uint32_t lmA = (wr * 32 + (lane & 15)) * RB + (lane >> 4) * 16;
    const uint32_t lmB = (wc * 64 + (lane & 15)) * RB + (lane >> 4) * 16;

    for (int c = 0; c < 16; ++c) {
        const uint32_t stg = sb + (c & 3) * SSTR;
        if (c <= 13)      CP_WAIT(2);
        else if (c == 14) CP_WAIT(1);
        else              CP_WAIT(0);
        __syncthreads();
        // stage (c+3)&3 == (c-1)&3: fully consumed by all warps before this sync
        if (c + 3 < 16) ISSUE(c + 3);

        uint32_t ah[2][4];
#pragma unroll
        for (int mr = 0; mr < 2; ++mr)
            LDSM4(ah[mr], stg + lmA + mr * 16 * RB);

#pragma unroll
        for (int nb = 0; nb < 4; ++nb) {
            if (!FULLN && nb >= nbLim) break;
            uint32_t bh[4];
            LDSM4(bh, stg + STG + lmB + nb * 16 * RB);
#pragma unroll
            for (int mr = 0; mr < 2; ++mr) {
                mma_f16(acc[mr][nb * 2 + 0], ah[mr], bh[0], bh[2]);
                mma_f16(acc[mr][nb * 2 + 1], ah[mr], bh[1], bh[3]);
            }
        }
    }

    // ---- epilogue ----
#pragma unroll
    for (int mr = 0; mr < 2; ++mr) {
        const int r0 = m0 + wr * 32 + mr * 16 + (lane >> 2);
#pragma unroll
        for (int f = 0; f < 8; ++f) {
            const int col = n0 + wc * 64 + f * 8 + (lane & 3) * 2;
            if (col >= N) continue;
            const float b0 = bias[col], b1 = bias[col + 1];
#pragma unroll
            for (int h = 0; h < 2; ++h) {
                const int r = r0 + h * 8;
                if (r >= M) continue;
                float x0 = acc[mr][f][h * 2 + 0] + b0;
                float x1 = acc[mr][f][h * 2 + 1] + b1;
                if (MODE == 1) {
                    x0 = gelu_exact(x0); x1 = gelu_exact(x1);
                    *reinterpret_cast<uint32_t*>(Ch + (size_t)r * DDIM + col) =
                        pack_h2(__float2half(x0), __float2half(x1));
                } else {
                    *reinterpret_cast<float2*>(Cf + (size_t)r * N + col) = make_float2(x0, x1);
                }
            }
        }
    }
#undef ISSUE
}

// ---------------- fp32 -> fp16 activation convert ------------------------------
__global__ __launch_bounds__(256)
void split_act(const float* __restrict__ x, __half* __restrict__ h, int n4) {
    const int i = blockIdx.x * 256 + threadIdx.x;
    if (i >= n4) return;
    const float4 v = __ldg(reinterpret_cast<const float4*>(x) + i);
    uint2 hv = make_uint2(pack_h2(__float2half(v.x), __float2half(v.y)),
                          pack_h2(__float2half(v.z), __float2half(v.w)));
    *reinterpret_cast<uint2*>(h + (size_t)i * 4) = hv;
}

// ---------------- weight transpose + fp16 convert (once per launch) -----------
__global__ __launch_bounds__(256)
void convert_weights(const float* __restrict__ Wv, const float* __restrict__ Wo,
                     const float* __restrict__ W1, const float* __restrict__ W2,
                     const float* __restrict__ Woff, const float* __restrict__ Wattn,
                     const float* __restrict__ boff, const float* __restrict__ battn) {
    const int b = blockIdx.x;
    const int k = threadIdx.x;
    if (b == 1168) {
        if (k < 96) g_boa[k] = boff[k];
        else if (k < 144) g_boa[k] = battn[k - 96];
        return;
    }
    const float* W; __half* oh; int n, nout, N;
    if (b < 256)       { W = Wv; oh = g_bv; n = b;        nout = n; N = 256; }
    else if (b < 512)  { W = Wo; oh = g_bo; n = b - 256;  nout = n; N = 256; }
    else if (b < 768)  { W = W1; oh = g_b1; n = b - 512;  nout = n; N = 256; }
    else if (b < 1024) { W = W2; oh = g_b2; n = b - 768;  nout = n; N = 256; }
    else {
        nout = b - 1024;  // 0..143
        oh = g_boaw;
        if (nout < 96) { W = Woff;  n = nout;      N = 96; }
        else           { W = Wattn; n = nout - 96; N = 48; }
    }
    oh[(size_t)nout * DDIM + k] = __float2half(W[(size_t)k * N + n]);
}

// ---------------- MSDA sampling v3: metadata lanes + shuffle-broadcast --------
__global__ __launch_bounds__(256)
void msda_sample_kernel(const float* __restrict__ oa, const float* __restrict__ v,
                        const float* __restrict__ ref, const int* __restrict__ ss,
                        __half* __restrict__ out) {
    const int q = blockIdx.x;
    const int h = threadIdx.x >> 5;
    const int lane = threadIdx.x & 31;
    const int corner = lane >> 3;
    const int cg = lane & 7;

    const int H = ss[0];
    const int W = ss[1];

    const float bx = __ldg(ref + q * 2 + 0) * (float)W - 0.5f;
    const float by = __ldg(ref + q * 2 + 1) * (float)H - 0.5f;

    const float* qa = oa + (size_t)q * 144;

    const int p_m = lane >> 2;
    const int c_m = lane & 3;
    const bool metaValid = (p_m < 6);

    float lg_own = metaValid ? __ldg(qa + 96 + h * 6 + p_m) : -1e30f;
    float mx = lg_own;
#pragma unroll
    for (int o = 4; o <= 16; o <<= 1)
        mx = fmaxf(mx, __shfl_xor_sync(0xffffffffu, mx, o));
    float e = metaValid ? __expf(lg_own - mx) : 0.f;
    float sum = e;
#pragma unroll
    for (int o = 4; o <= 16; o <<= 1)
        sum += __shfl_xor_sync(0xffffffffu, sum, o);
    const float a_own = e / sum;

    const int pp = metaValid ? p_m : 0;
    const float ox = __ldg(qa + h * 12 + pp * 2 + 0);
    const float oy = __ldg(qa + h * 12 + pp * 2 + 1);
    const float lx = bx + ox;
    const float ly = by + oy;
    const float x0f = floorf(lx);
    const float y0f = floorf(ly);
    const float fx = lx - x0f;
    const float fy = ly - y0f;
    const int dxm = c_m & 1;
    const int dym = c_m >> 1;
    const int xi = (int)x0f + dxm;
    const int yi = (int)y0f + dym;
    const float wx = dxm ? fx : 1.f - fx;
    const float wy = dym ? fy : 1.f - fy;
    const bool valid = metaValid & (xi >= 0) & (xi < W) & (yi >= 0) & (yi < H);
    const float wv = valid ? a_own * wx * wy : 0.f;
    const uint32_t xc = (uint32_t)min(max(xi, 0), W - 1);
    const uint32_t yc = (uint32_t)min(max(yi, 0), H - 1);
    const uint32_t off_own = (yc * (uint32_t)W + xc) * 64u;

    const float4* vh = reinterpret_cast<const float4*>(v) + (h * 8 + cg);
    float4 acc = make_float4(0.f, 0.f, 0.f, 0.f);

#pragma unroll
    for (int p = 0; p < 6; ++p) {
        const int src = p * 4 + corner;
        const uint32_t off = __shfl_sync(0xffffffffu, off_own, src);
        const float w = __shfl_sync(0xffffffffu, wv, src);
        const float4 val = __ldg(vh + off);
        acc.x += w * val.x;
        acc.y += w * val.y;
        acc.z += w * val.z;
        acc.w += w * val.w;
    }

#pragma unroll
    for (int o = 8; o <= 16; o <<= 1) {
        acc.x += __shfl_xor_sync(0xffffffffu, acc.x, o);
        acc.y += __shfl_xor_sync(0xffffffffu, acc.y, o);
        acc.z += __shfl_xor_sync(0xffffffffu, acc.z, o);
        acc.w += __shfl_xor_sync(0xffffffffu, acc.w, o);
    }
    if (lane < 8) {
        uint2 hv = make_uint2(pack_h2(__float2half(acc.x), __float2half(acc.y)),
                              pack_h2(__float2half(acc.z), __float2half(acc.w)));
        *reinterpret_cast<uint2*>(out + (size_t)q * DDIM + h * 32 + cg * 4) = hv;
    }
}

// ---------------- fused residual + LayerNorm: one warp per row -----------------
template<int SPLIT>
__global__ __launch_bounds__(256)
void ln_kernel(const float* __restrict__ x, const float* __restrict__ res,
               const float* __restrict__ g, const float* __restrict__ b,
               float* __restrict__ out, __half* __restrict__ out16, int M) {
    const int row = blockIdx.x * 8 + (threadIdx.x >> 5);
    if (row >= M) return;
    const int lane = threadIdx.x & 31;
    const size_t base = (size_t)row * DDIM + lane * 8;

    float4 v0 = *reinterpret_cast<const float4*>(x + base);
    float4 v1 = *reinterpret_cast<const float4*>(x + base + 4);
    const float4 r0 = *reinterpret_cast<const float4*>(res + base);
    const float4 r1 = *reinterpret_cast<const float4*>(res + base + 4);
    v0.x += r0.x; v0.y += r0.y; v0.z += r0.z; v0.w += r0.w;
    v1.x += r1.x; v1.y += r1.y; v1.z += r1.z; v1.w += r1.w;

    float s  = v0.x + v0.y + v0.z + v0.w + v1.x + v1.y + v1.z + v1.w;
    float s2 = v0.x * v0.x + v0.y * v0.y + v0.z * v0.z + v0.w * v0.w
             + v1.x * v1.x + v1.y * v1.y + v1.z * v1.z + v1.w * v1.w;
#pragma unroll
    for (int o = 16; o; o >>= 1) {
        s  += __shfl_xor_sync(0xffffffffu, s, o);
        s2 += __shfl_xor_sync(0xffffffffu, s2, o);
    }
    const float mean = s * (1.f / 256.f);
    const float var  = s2 * (1.f / 256.f) - mean * mean;
    const float rstd = rsqrtf(var + 1e-5f);

    const float4 g0 = *reinterpret_cast<const float4*>(g + lane * 8);
    const float4 g1 = *reinterpret_cast<const float4*>(g + lane * 8 + 4);
    const float4 b0 = *reinterpret_cast<const float4*>(b + lane * 8);
    const float4 b1 = *reinterpret_cast<const float4*>(b + lane * 8 + 4);

    float4 o0, o1;
    o0.x = (v0.x - mean) * rstd * g0.x + b0.x;
    o0.y = (v0.y - mean) * rstd * g0.y + b0.y;
    o0.z = (v0.z - mean) * rstd * g0.z + b0.z;
    o0.w = (v0.w - mean) * rstd * g0.w + b0.w;
    o1.x = (v1.x - mean) * rstd * g1.x + b1.x;
    o1.y = (v1.y - mean) * rstd * g1.y + b1.y;
    o1.z = (v1.z - mean) * rstd * g1.z + b1.z;
    o1.w = (v1.w - mean) * rstd * g1.w + b1.w;
    *reinterpret_cast<float4*>(out + base)     = o0;
    *reinterpret_cast<float4*>(out + base + 4) = o1;
    if (SPLIT) {
        uint4 hv;
        hv.x = pack_h2(__float2half(o0.x), __float2half(o0.y));
        hv.y = pack_h2(__float2half(o0.z), __float2half(o0.w));
        hv.z = pack_h2(__float2half(o1.x), __float2half(o1.y));
        hv.w = pack_h2(__float2half(o1.z), __float2half(o1.w));
        *reinterpret_cast<uint4*>(out16 + base) = hv;
    }
}

// ---------------- launch --------------------------------------------------------
extern "C" void kernel_launch(void* const* d_in, const int* in_sizes, int n_in,
                              void* d_out, int out_size) {
    const float* query  = (const float*)d_in[0];
    const float* value  = (const float*)d_in[1];
    const float* refp   = (const float*)d_in[2];
    const int*   ss     = (const int*)d_in[3];
    const float* W_off  = (const float*)d_in[5];
    const float* b_off  = (const float*)d_in[6];
    const float* W_attn = (const float*)d_in[7];
    const float* b_attn = (const float*)d_in[8];
    const float* W_val  = (const float*)d_in[9];
    const float* b_val  = (const float*)d_in[10];
    const float* W_out  = (const float*)d_in[11];
    const float* b_out  = (const float*)d_in[12];
    const float* ln1_g  = (const float*)d_in[13];
    const float* ln1_b  = (const float*)d_in[14];
    const float* W1     = (const float*)d_in[15];
    const float* b1     = (const float*)d_in[16];
    const float* W2     = (const float*)d_in[17];
    const float* b2     = (const float*)d_in[18];
    const float* ln2_g  = (const float*)d_in[19];
    const float* ln2_b  = (const float*)d_in[20];
    float* out = (float*)d_out;

    const int M  = in_sizes[0] / DDIM;
    const int Mv = in_sizes[1] / DDIM;

    float *pv, *poa, *ptmp, *py, *pboa;
    __half *q16, *a16, *m16, *y16, *h16;
    __half *bv, *bo, *b1w, *b2w, *boaw;
    cudaGetSymbolAddress((void**)&pv,    g_v);
    cudaGetSymbolAddress((void**)&poa,   g_oa);
    cudaGetSymbolAddress((void**)&ptmp,  g_tmp);
    cudaGetSymbolAddress((void**)&py,    g_y);
    cudaGetSymbolAddress((void**)&pboa,  g_boa);
    cudaGetSymbolAddress((void**)&q16,   g_q16);
    cudaGetSymbolAddress((void**)&a16,   g_a16);
    cudaGetSymbolAddress((void**)&m16,   g_m16);
    cudaGetSymbolAddress((void**)&y16,   g_y16);
    cudaGetSymbolAddress((void**)&h16,   g_h16);
    cudaGetSymbolAddress((void**)&bv,    g_bv);
    cudaGetSymbolAddress((void**)&bo,    g_bo);
    cudaGetSymbolAddress((void**)&b1w,   g_b1);
    cudaGetSymbolAddress((void**)&b2w,   g_b2);
    cudaGetSymbolAddress((void**)&boaw,  g_boaw);

    const int SMEM = 8 * 128 * 48;  // 49152 bytes (4 stages x 12KB)
    cudaFuncSetAttribute((gemm_mma<0, 1>), cudaFuncAttributeMaxDynamicSharedMemorySize, SMEM);
    cudaFuncSetAttribute((gemm_mma<1, 1>), cudaFuncAttributeMaxDynamicSharedMemorySize, SMEM);
    cudaFuncSetAttribute((gemm_mma<0, 0>), cudaFuncAttributeMaxDynamicSharedMemorySize, SMEM);

    const int gM  = (M + 127) / 128;
    const int gMv = (Mv + 127) / 128;
    const int gLN = (M + 7) / 8;

    // 0) weights -> transposed fp16; activations -> fp16
    convert_weights<<<1169, 256>>>(W_val, W_out, W1, W2, W_off, W_attn, b_off, b_attn);
    split_act<<<(M * 64 + 255) / 256, 256>>>(query, q16, M * 64);
    split_act<<<(Mv * 64 + 255) / 256, 256>>>(value, a16, Mv * 64);
    // 1) value projection
    gemm_mma<0, 1><<<dim3(2, gMv), 256, SMEM>>>(a16, bv, b_val, pv, nullptr, Mv, DDIM);
    // 2) fused offsets+attn logits GEMM (N=144, statically clamped)
    gemm_mma<0, 0><<<dim3(2, gM), 256, SMEM>>>(q16, boaw, pboa, poa, nullptr, M, 144);
    // 3) deformable sampling -> fp16
    msda_sample_kernel<<<M, 256>>>(poa, pv, refp, ss, m16);
    // 4) output projection + residual + LN1
    gemm_mma<0, 1><<<dim3(2, gM), 256, SMEM>>>(m16, bo, b_out, ptmp, nullptr, M, DDIM);
    ln_kernel<1><<<gLN, 256>>>(ptmp, query, ln1_g, ln1_b, py, y16, M);
    // 5) FFN
    gemm_mma<1, 1><<<dim3(2, gM), 256, SMEM>>>(y16, b1w, b1, nullptr, h16, M, DDIM);
    gemm_mma<0, 1><<<dim3(2, gM), 256, SMEM>>>(h16, b2w, b2, ptmp, nullptr, M, DDIM);
    ln_kernel<0><<<gLN, 256>>>(ptmp, py, ln2_g, ln2_b, out, nullptr, M);
}